// round 1
// baseline (speedup 1.0000x reference)
#include <cuda_runtime.h>
#include <math.h>

#define T_   1024
#define HID_ 5120
#define NH_  128
#define DN_  128
#define DR_  64
#define DV_  128
#define QLR_ 1536
#define KVLR_ 512
#define DQK_ 192    // DN+DR
#define DKV_ 256    // DN+DV
#define NQKV_ 2112  // QLR+KVLR+DR

// ---------------- scratch (device globals; no runtime allocation) -----------
__device__ float g_qkv [T_ * NQKV_];          // 8.7 MB
__device__ float g_qan [T_ * QLR_];           // 6.3 MB
__device__ float g_kvan[T_ * KVLR_];          // 2.1 MB
__device__ float g_q   [T_ * NH_ * DQK_];     // 100.7 MB
__device__ float g_kv  [T_ * NH_ * DKV_];     // 134.2 MB
__device__ float g_kpe [T_ * DR_];            // 0.26 MB
__device__ float g_attn[T_ * NH_ * DV_];      // 67.1 MB
__device__ float g_cos [T_ * 32];
__device__ float g_sin [T_ * 32];

// ---------------- generic fp32 GEMM: C[M,N] = A[M,K] @ B[K,N] ---------------
// 128x128 tile, BK=8, 256 threads, 8x8 per-thread microtile.
// Requires: M % 128 == 0, K % 8 == 0, N % 8 == 0 (N guarded for partial tiles).
__global__ void sgemm128(const float* __restrict__ A, const float* __restrict__ B,
                         float* __restrict__ C, int M, int N, int K) {
    __shared__ float As[8][128];
    __shared__ float Bs[8][128];
    const int bm = blockIdx.y * 128;
    const int bn = blockIdx.x * 128;
    const int tid = threadIdx.x;
    const int tx = tid & 15, ty = tid >> 4;
    const int m0 = ty * 8, n0 = tx * 8;

    const int arow = tid >> 1;           // 0..127
    const int acol = (tid & 1) * 4;      // 0 or 4
    const int brow = tid >> 5;           // 0..7
    const int bcol = (tid & 31) * 4;     // 0..124

    float acc[8][8];
#pragma unroll
    for (int i = 0; i < 8; i++)
#pragma unroll
        for (int j = 0; j < 8; j++) acc[i][j] = 0.f;

    for (int k0 = 0; k0 < K; k0 += 8) {
        float4 a = *(const float4*)(A + (size_t)(bm + arow) * K + k0 + acol);
        As[acol + 0][arow] = a.x;
        As[acol + 1][arow] = a.y;
        As[acol + 2][arow] = a.z;
        As[acol + 3][arow] = a.w;
        if (bn + bcol < N) {
            *(float4*)&Bs[brow][bcol] =
                *(const float4*)(B + (size_t)(k0 + brow) * N + bn + bcol);
        } else {
            Bs[brow][bcol] = Bs[brow][bcol + 1] = Bs[brow][bcol + 2] = Bs[brow][bcol + 3] = 0.f;
        }
        __syncthreads();
#pragma unroll
        for (int k = 0; k < 8; k++) {
            float ra[8], rb[8];
#pragma unroll
            for (int i = 0; i < 8; i++) ra[i] = As[k][m0 + i];
#pragma unroll
            for (int j = 0; j < 8; j++) rb[j] = Bs[k][n0 + j];
#pragma unroll
            for (int i = 0; i < 8; i++)
#pragma unroll
                for (int j = 0; j < 8; j++) acc[i][j] = fmaf(ra[i], rb[j], acc[i][j]);
        }
        __syncthreads();
    }
    if (bn + n0 < N) {
#pragma unroll
        for (int i = 0; i < 8; i++) {
            float* cr = C + (size_t)(bm + m0 + i) * N + bn + n0;
            *(float4*)cr       = make_float4(acc[i][0], acc[i][1], acc[i][2], acc[i][3]);
            *(float4*)(cr + 4) = make_float4(acc[i][4], acc[i][5], acc[i][6], acc[i][7]);
        }
    }
}

// ---------------- rmsnorm (one row per block) -------------------------------
__global__ void rmsnorm_kernel(const float* __restrict__ x, int srcStride, int srcOff, int W,
                               const float* __restrict__ w, float* __restrict__ y) {
    const int row = blockIdx.x;
    const float* xr = x + (size_t)row * srcStride + srcOff;
    float ss = 0.f;
    for (int c = threadIdx.x; c < W; c += blockDim.x) {
        float v = xr[c];
        ss += v * v;
    }
    __shared__ float red[32];
#pragma unroll
    for (int o = 16; o; o >>= 1) ss += __shfl_xor_sync(0xffffffffu, ss, o);
    if ((threadIdx.x & 31) == 0) red[threadIdx.x >> 5] = ss;
    __syncthreads();
    if (threadIdx.x < 32) {
        float v = (threadIdx.x < (blockDim.x >> 5)) ? red[threadIdx.x] : 0.f;
#pragma unroll
        for (int o = 16; o; o >>= 1) v += __shfl_xor_sync(0xffffffffu, v, o);
        red[threadIdx.x] = v;
    }
    __syncthreads();
    const float rstd = rsqrtf(red[0] / (float)W + 1e-6f);
    float* yr = y + (size_t)row * W;
    for (int c = threadIdx.x; c < W; c += blockDim.x) yr[c] = xr[c] * rstd * w[c];
}

// ---------------- RoPE tables (double precision for accuracy) ---------------
__global__ void rope_tab_kernel(const int* __restrict__ pos) {
    const int t = blockIdx.x, i = threadIdx.x; // i in [0,32)
    double inv = pow(10000.0, -(double)i / 32.0);
    double f = (double)pos[t] * inv;
    double s, c;
    sincos(f, &s, &c);
    g_cos[t * 32 + i] = (float)c;
    g_sin[t * 32 + i] = (float)s;
}

// RoPE applied in-place to q (last DR dims of each head) ---------------------
__global__ void rope_q_kernel() {
    const int h = blockIdx.x, t = blockIdx.y, i = threadIdx.x; // i in [0,32)
    const float c = g_cos[t * 32 + i];
    const float s = g_sin[t * 32 + i];
    float* base = g_q + ((size_t)t * NH_ + h) * DQK_ + DN_ + 2 * i;
    const float x1 = base[0], x2 = base[1];
    base[0] = x1 * c - x2 * s;
    base[1] = x2 * c + x1 * s;
}

// RoPE on k_pe (slice of qkv) -> g_kpe ---------------------------------------
__global__ void rope_k_kernel() {
    const int t = blockIdx.x, i = threadIdx.x; // i in [0,32)
    const float c = g_cos[t * 32 + i];
    const float s = g_sin[t * 32 + i];
    const float* src = g_qkv + (size_t)t * NQKV_ + (QLR_ + KVLR_) + 2 * i;
    const float x1 = src[0], x2 = src[1];
    g_kpe[t * DR_ + 2 * i]     = x1 * c - x2 * s;
    g_kpe[t * DR_ + 2 * i + 1] = x2 * c + x1 * s;
}

// ---------------- flash attention: 1 CTA = (head, 64-row q block) -----------
#define QB_ 64
#define KB_ 64

struct AttnSmem {
    float Q[QB_][DQK_ + 1];
    float K[KB_][DQK_ + 1];
    float V[KB_][DV_];
    float P[QB_][KB_ + 1];
    float rowM[QB_], rowL[QB_], rowScale[QB_];
};

__global__ void attn_kernel() {
    extern __shared__ char smem_raw[];
    AttnSmem& sm = *(AttnSmem*)smem_raw;
    const int h = blockIdx.x;
    const int qb = blockIdx.y;
    const int tid = threadIdx.x;
    const int tx = tid & 15, ty = tid >> 4;
    const int r0 = ty * 4;       // rows of this thread (S & O)
    const int c0 = tx * 4;       // S cols
    const int c0v = tx * 8;      // O cols

    // load Q block
    for (int idx = tid; idx < QB_ * DQK_; idx += 256) {
        int r = idx / DQK_, c = idx % DQK_;
        sm.Q[r][c] = g_q[((size_t)(qb * QB_ + r) * NH_ + h) * DQK_ + c];
    }
    if (tid < QB_) {
        sm.rowM[tid] = -1e30f;
        sm.rowL[tid] = 0.f;
    }
    float o[4][8];
#pragma unroll
    for (int i = 0; i < 4; i++)
#pragma unroll
        for (int j = 0; j < 8; j++) o[i][j] = 0.f;
    __syncthreads();

    const float scaling = rsqrtf((float)DQK_);

    for (int kc = 0; kc <= qb; kc++) {
        // K chunk (nope part from kv, pe part from roped k_pe) + V chunk
        for (int idx = tid; idx < KB_ * DQK_; idx += 256) {
            int r = idx / DQK_, c = idx % DQK_;
            int tk = kc * KB_ + r;
            sm.K[r][c] = (c < DN_) ? g_kv[((size_t)tk * NH_ + h) * DKV_ + c]
                                   : g_kpe[tk * DR_ + (c - DN_)];
        }
        for (int idx = tid; idx < KB_ * DV_; idx += 256) {
            int r = idx / DV_, c = idx % DV_;
            int tk = kc * KB_ + r;
            sm.V[r][c] = g_kv[((size_t)tk * NH_ + h) * DKV_ + DN_ + c];
        }
        __syncthreads();

        // S = Q K^T  (4x4 per thread)
        float s4[4][4];
#pragma unroll
        for (int i = 0; i < 4; i++)
#pragma unroll
            for (int j = 0; j < 4; j++) s4[i][j] = 0.f;
#pragma unroll 4
        for (int k = 0; k < DQK_; k++) {
            float a0 = sm.Q[r0][k], a1 = sm.Q[r0 + 1][k], a2 = sm.Q[r0 + 2][k], a3 = sm.Q[r0 + 3][k];
            float b0 = sm.K[c0][k], b1 = sm.K[c0 + 1][k], b2 = sm.K[c0 + 2][k], b3 = sm.K[c0 + 3][k];
            s4[0][0] = fmaf(a0, b0, s4[0][0]); s4[0][1] = fmaf(a0, b1, s4[0][1]);
            s4[0][2] = fmaf(a0, b2, s4[0][2]); s4[0][3] = fmaf(a0, b3, s4[0][3]);
            s4[1][0] = fmaf(a1, b0, s4[1][0]); s4[1][1] = fmaf(a1, b1, s4[1][1]);
            s4[1][2] = fmaf(a1, b2, s4[1][2]); s4[1][3] = fmaf(a1, b3, s4[1][3]);
            s4[2][0] = fmaf(a2, b0, s4[2][0]); s4[2][1] = fmaf(a2, b1, s4[2][1]);
            s4[2][2] = fmaf(a2, b2, s4[2][2]); s4[2][3] = fmaf(a2, b3, s4[2][3]);
            s4[3][0] = fmaf(a3, b0, s4[3][0]); s4[3][1] = fmaf(a3, b1, s4[3][1]);
            s4[3][2] = fmaf(a3, b2, s4[3][2]); s4[3][3] = fmaf(a3, b3, s4[3][3]);
        }
        const bool diag = (kc == qb);
#pragma unroll
        for (int i = 0; i < 4; i++)
#pragma unroll
            for (int j = 0; j < 4; j++) {
                int rg = qb * QB_ + r0 + i, cg = kc * KB_ + c0 + j;
                float v = s4[i][j] * scaling;
                if (diag && cg > rg) v = -1e30f;
                sm.P[r0 + i][c0 + j] = v;
            }
        __syncthreads();

        // online softmax: 4 threads per row
        {
            const int row = tid >> 2, lane = tid & 3;
            float mloc = -1e30f;
#pragma unroll
            for (int c = 0; c < 16; c++) mloc = fmaxf(mloc, sm.P[row][lane * 16 + c]);
            mloc = fmaxf(mloc, __shfl_xor_sync(0xffffffffu, mloc, 1));
            mloc = fmaxf(mloc, __shfl_xor_sync(0xffffffffu, mloc, 2));
            const float mprev = sm.rowM[row];
            const float mnew = fmaxf(mprev, mloc);
            float lsum = 0.f;
#pragma unroll
            for (int c = 0; c < 16; c++) {
                float p = __expf(sm.P[row][lane * 16 + c] - mnew);
                sm.P[row][lane * 16 + c] = p;
                lsum += p;
            }
            lsum += __shfl_xor_sync(0xffffffffu, lsum, 1);
            lsum += __shfl_xor_sync(0xffffffffu, lsum, 2);
            if (lane == 0) {
                float sc = __expf(mprev - mnew);
                sm.rowScale[row] = sc;
                sm.rowM[row] = mnew;
                sm.rowL[row] = sm.rowL[row] * sc + lsum;
            }
        }
        __syncthreads();

        // rescale O, then O += P @ V
#pragma unroll
        for (int i = 0; i < 4; i++) {
            const float sc = sm.rowScale[r0 + i];
#pragma unroll
            for (int j = 0; j < 8; j++) o[i][j] *= sc;
        }
#pragma unroll 2
        for (int kk = 0; kk < KB_; kk++) {
            const float p0 = sm.P[r0][kk], p1 = sm.P[r0 + 1][kk];
            const float p2 = sm.P[r0 + 2][kk], p3 = sm.P[r0 + 3][kk];
            const float4 va = *(const float4*)&sm.V[kk][c0v];
            const float4 vb = *(const float4*)&sm.V[kk][c0v + 4];
            o[0][0] = fmaf(p0, va.x, o[0][0]); o[0][1] = fmaf(p0, va.y, o[0][1]);
            o[0][2] = fmaf(p0, va.z, o[0][2]); o[0][3] = fmaf(p0, va.w, o[0][3]);
            o[0][4] = fmaf(p0, vb.x, o[0][4]); o[0][5] = fmaf(p0, vb.y, o[0][5]);
            o[0][6] = fmaf(p0, vb.z, o[0][6]); o[0][7] = fmaf(p0, vb.w, o[0][7]);
            o[1][0] = fmaf(p1, va.x, o[1][0]); o[1][1] = fmaf(p1, va.y, o[1][1]);
            o[1][2] = fmaf(p1, va.z, o[1][2]); o[1][3] = fmaf(p1, va.w, o[1][3]);
            o[1][4] = fmaf(p1, vb.x, o[1][4]); o[1][5] = fmaf(p1, vb.y, o[1][5]);
            o[1][6] = fmaf(p1, vb.z, o[1][6]); o[1][7] = fmaf(p1, vb.w, o[1][7]);
            o[2][0] = fmaf(p2, va.x, o[2][0]); o[2][1] = fmaf(p2, va.y, o[2][1]);
            o[2][2] = fmaf(p2, va.z, o[2][2]); o[2][3] = fmaf(p2, va.w, o[2][3]);
            o[2][4] = fmaf(p2, vb.x, o[2][4]); o[2][5] = fmaf(p2, vb.y, o[2][5]);
            o[2][6] = fmaf(p2, vb.z, o[2][6]); o[2][7] = fmaf(p2, vb.w, o[2][7]);
            o[3][0] = fmaf(p3, va.x, o[3][0]); o[3][1] = fmaf(p3, va.y, o[3][1]);
            o[3][2] = fmaf(p3, va.z, o[3][2]); o[3][3] = fmaf(p3, va.w, o[3][3]);
            o[3][4] = fmaf(p3, vb.x, o[3][4]); o[3][5] = fmaf(p3, vb.y, o[3][5]);
            o[3][6] = fmaf(p3, vb.z, o[3][6]); o[3][7] = fmaf(p3, vb.w, o[3][7]);
        }
        __syncthreads();
    }

    // finalize: divide by row sums and write out [T][NH*DV]
#pragma unroll
    for (int i = 0; i < 4; i++) {
        const float inv = 1.f / sm.rowL[r0 + i];
        float* dst = g_attn + (size_t)(qb * QB_ + r0 + i) * (NH_ * DV_) + h * DV_ + c0v;
#pragma unroll
        for (int j = 0; j < 8; j++) dst[j] = o[i][j] * inv;
    }
}

// ---------------- launch ----------------------------------------------------
extern "C" void kernel_launch(void* const* d_in, const int* in_sizes, int n_in,
                              void* d_out, int out_size) {
    const int*   positions = (const int*)d_in[0];
    const float* hidden    = (const float*)d_in[1];
    const float* w_qkv_a   = (const float*)d_in[2];
    const float* q_a_ln_w  = (const float*)d_in[3];
    const float* w_q_b     = (const float*)d_in[4];
    const float* kv_a_ln_w = (const float*)d_in[5];
    const float* w_kv_b    = (const float*)d_in[6];
    const float* w_o       = (const float*)d_in[7];
    float* out = (float*)d_out;

    float *p_qkv, *p_qan, *p_kvan, *p_q, *p_kv, *p_attn;
    cudaGetSymbolAddress((void**)&p_qkv,  g_qkv);
    cudaGetSymbolAddress((void**)&p_qan,  g_qan);
    cudaGetSymbolAddress((void**)&p_kvan, g_kvan);
    cudaGetSymbolAddress((void**)&p_q,    g_q);
    cudaGetSymbolAddress((void**)&p_kv,   g_kv);
    cudaGetSymbolAddress((void**)&p_attn, g_attn);

    // GEMM1: qkv = hidden @ w_qkv_a   [1024,5120]x[5120,2112]
    sgemm128<<<dim3((NQKV_ + 127) / 128, T_ / 128), 256>>>(hidden, w_qkv_a, p_qkv, T_, NQKV_, HID_);

    // rmsnorms
    rmsnorm_kernel<<<T_, 256>>>(p_qkv, NQKV_, 0,    QLR_,  q_a_ln_w,  p_qan);
    rmsnorm_kernel<<<T_, 256>>>(p_qkv, NQKV_, QLR_, KVLR_, kv_a_ln_w, p_kvan);

    // GEMM2: q = q_a_n @ w_q_b   [1024,1536]x[1536,24576]
    sgemm128<<<dim3((NH_ * DQK_) / 128, T_ / 128), 256>>>(p_qan, w_q_b, p_q, T_, NH_ * DQK_, QLR_);
    // GEMM3: kv = kv_a_n @ w_kv_b [1024,512]x[512,32768]
    sgemm128<<<dim3((NH_ * DKV_) / 128, T_ / 128), 256>>>(p_kvan, w_kv_b, p_kv, T_, NH_ * DKV_, KVLR_);

    // RoPE
    rope_tab_kernel<<<T_, 32>>>(positions);
    rope_q_kernel<<<dim3(NH_, T_), 32>>>();
    rope_k_kernel<<<T_, 32>>>();

    // attention
    static const size_t attn_smem = sizeof(AttnSmem);
    cudaFuncSetAttribute(attn_kernel, cudaFuncAttributeMaxDynamicSharedMemorySize, (int)attn_smem);
    attn_kernel<<<dim3(NH_, T_ / QB_), 256, attn_smem>>>();

    // GEMM4: out = attn @ w_o  [1024,16384]x[16384,5120]
    sgemm128<<<dim3(HID_ / 128, T_ / 128), 256>>>(p_attn, w_o, out, T_, HID_, NH_ * DV_);
}

// round 3
// speedup vs baseline: 2.0308x; 2.0308x over previous
#include <cuda_runtime.h>
#include <cuda_bf16.h>
#include <math.h>
#include <stdint.h>

#define T_   1024
#define HID_ 5120
#define NH_  128
#define DN_  128
#define DR_  64
#define DV_  128
#define QLR_ 1536
#define KVLR_ 512
#define DQK_ 192    // DN+DR
#define DKV_ 256    // DN+DV
#define NQKV_ 2112  // QLR+KVLR+DR
#define NQKV_PAD_ 2304

// ---------------- fp32 scratch ----------------------------------------------
__device__ float g_qkv [T_ * NQKV_];
__device__ float g_qan [T_ * QLR_];
__device__ float g_kvan[T_ * KVLR_];
__device__ float g_q   [T_ * NH_ * DQK_];
__device__ float g_kv  [T_ * NH_ * DKV_];
__device__ float g_kpe [T_ * DR_];
__device__ float g_attn[T_ * NH_ * DV_];
__device__ float g_cos [T_ * 32];
__device__ float g_sin [T_ * 32];

// ---------------- bf16 split scratch ----------------------------------------
__device__ __nv_bfloat16 g_w1h[NQKV_PAD_ * HID_];     // w_qkv_a^T hi
__device__ __nv_bfloat16 g_w1l[NQKV_PAD_ * HID_];
__device__ __nv_bfloat16 g_w2h[(NH_*DQK_) * QLR_];    // w_q_b^T
__device__ __nv_bfloat16 g_w2l[(NH_*DQK_) * QLR_];
__device__ __nv_bfloat16 g_w3h[(NH_*DKV_) * KVLR_];   // w_kv_b^T
__device__ __nv_bfloat16 g_w3l[(NH_*DKV_) * KVLR_];
__device__ __nv_bfloat16 g_w4h[HID_ * (NH_*DV_)];     // w_o^T
__device__ __nv_bfloat16 g_w4l[HID_ * (NH_*DV_)];
__device__ __nv_bfloat16 g_ah [T_ * (NH_*DV_)];       // reusable A hi (max 1024x16384)
__device__ __nv_bfloat16 g_al [T_ * (NH_*DV_)];       // reusable A lo

// ======================= PTX helpers =========================================
__device__ __forceinline__ uint32_t smem_u32(const void* p) {
    uint32_t a;
    asm("{ .reg .u64 t; cvta.to.shared.u64 t, %1; cvt.u32.u64 %0, t; }" : "=r"(a) : "l"(p));
    return a;
}

#define CP_ASYNC16(dst_u32, src_ptr) \
    asm volatile("cp.async.cg.shared.global [%0], [%1], 16;" :: "r"(dst_u32), "l"(src_ptr))
#define CP_COMMIT() asm volatile("cp.async.commit_group;" ::: "memory")
#define CP_WAIT1()  asm volatile("cp.async.wait_group 1;" ::: "memory")

#define LDSM_X4(r0, r1, r2, r3, addr) \
    asm volatile("ldmatrix.sync.aligned.m8n8.x4.shared.b16 {%0,%1,%2,%3}, [%4];" \
        : "=r"(r0), "=r"(r1), "=r"(r2), "=r"(r3) : "r"(addr))
#define LDSM_X2(r0, r1, addr) \
    asm volatile("ldmatrix.sync.aligned.m8n8.x2.shared.b16 {%0,%1}, [%2];" \
        : "=r"(r0), "=r"(r1) : "r"(addr))

#define MMA16816(d, a, b) \
    asm volatile("mma.sync.aligned.m16n8k16.row.col.f32.bf16.bf16.f32 " \
        "{%0,%1,%2,%3},{%4,%5,%6,%7},{%8,%9},{%0,%1,%2,%3};" \
        : "+f"((d)[0]), "+f"((d)[1]), "+f"((d)[2]), "+f"((d)[3]) \
        : "r"((a)[0]), "r"((a)[1]), "r"((a)[2]), "r"((a)[3]), "r"((b)[0]), "r"((b)[1]))

// ======================= bf16 split conversion ===============================
__device__ __forceinline__ void split2(float v, __nv_bfloat16& h, __nv_bfloat16& l) {
    h = __float2bfloat16_rn(v);
    l = __float2bfloat16_rn(v - __bfloat162float(h));
}

__global__ void convA_kernel(const float* __restrict__ A,
                             __nv_bfloat16* __restrict__ H,
                             __nv_bfloat16* __restrict__ L, int n) {
    int i = blockIdx.x * blockDim.x + threadIdx.x;
    if (i < n) {
        __nv_bfloat16 h, l;
        split2(A[i], h, l);
        H[i] = h; L[i] = l;
    }
}

// B [K,N] fp32 -> Bt hi/lo [Npad,K] bf16 (transpose + split, pad rows zero)
__global__ void convBT_kernel(const float* __restrict__ B,
                              __nv_bfloat16* __restrict__ TH,
                              __nv_bfloat16* __restrict__ TL,
                              int K, int N) {
    __shared__ float tile[32][33];
    const int k0 = blockIdx.x * 32, n0 = blockIdx.y * 32;
    const int tx = threadIdx.x, ty = threadIdx.y; // 32 x 8
    for (int i = ty; i < 32; i += 8) {
        int n = n0 + tx;
        tile[i][tx] = (n < N) ? B[(size_t)(k0 + i) * N + n] : 0.f;
    }
    __syncthreads();
    for (int i = ty; i < 32; i += 8) {
        float v = tile[tx][i];
        __nv_bfloat16 h, l;
        split2(v, h, l);
        size_t off = (size_t)(n0 + i) * K + k0 + tx;
        TH[off] = h; TL[off] = l;
    }
}

// ======================= HMMA split GEMM =====================================
// C[M,N] = A[M,K] @ B^T[N,K]; A,B given as bf16 hi/lo pairs, K-major.
// C = Ah*Bh + Ah*Bl + Al*Bh  (3-term split, fp32 accum).
// CTA: 128x128 tile, BK=32, 256 threads = 8 warps (2m x 4n), warp tile 64x32.
#define GPITCH 80                 // bytes per 32-col bf16 row (64B data + 16B pad)
#define GTILE  (128 * GPITCH)     // 10240 B per matrix per stage
#define GSTAGE (4 * GTILE)        // Ah, Al, Bh, Bl
#define GEMM_SMEM (2 * GSTAGE)    // 81920 B

__global__ void __launch_bounds__(256, 2)
gemm_hmma(const __nv_bfloat16* __restrict__ Ah, const __nv_bfloat16* __restrict__ Al,
          const __nv_bfloat16* __restrict__ Bh, const __nv_bfloat16* __restrict__ Bl,
          float* __restrict__ C, int Nreal, int ldC, int K) {
    extern __shared__ char smem[];
    const uint32_t sb = smem_u32(smem);
    const int tid  = threadIdx.x;
    const int wid  = tid >> 5;
    const int lane = tid & 31;
    const int wm   = wid & 1;      // 0..1 -> 64-row slab
    const int wn   = wid >> 1;     // 0..3 -> 32-col slab
    const int bm   = blockIdx.y * 128;
    const int bn   = blockIdx.x * 128;
    const int nchunks = K >> 5;

    // cp.async addressing: chunk ch (0..511) -> row=ch>>2, 16B col=ch&3
    const int r0c = tid >> 2, c40 = (tid & 3);

    auto issue = [&](int stage, int c) {
        const int k0 = c << 5;
        const uint32_t st = sb + stage * GSTAGE;
#pragma unroll
        for (int p = 0; p < 2; p++) {
            const int row = r0c + p * 64;
            const uint32_t doff = row * GPITCH + c40 * 16;
            const size_t goA = (size_t)(bm + row) * K + k0 + c40 * 8;
            const size_t goB = (size_t)(bn + row) * K + k0 + c40 * 8;
            CP_ASYNC16(st + 0 * GTILE + doff, Ah + goA);
            CP_ASYNC16(st + 1 * GTILE + doff, Al + goA);
            CP_ASYNC16(st + 2 * GTILE + doff, Bh + goB);
            CP_ASYNC16(st + 3 * GTILE + doff, Bl + goB);
        }
    };

    float acc[4][4][4];
#pragma unroll
    for (int i = 0; i < 4; i++)
#pragma unroll
        for (int j = 0; j < 4; j++)
#pragma unroll
            for (int q = 0; q < 4; q++) acc[i][j][q] = 0.f;

    // ldmatrix per-thread base offsets
    uint32_t aoff[4], boff[4];
#pragma unroll
    for (int mf = 0; mf < 4; mf++) {
        const int row = wm * 64 + mf * 16 + (lane & 15);
        aoff[mf] = row * GPITCH + ((lane >> 4) & 1) * 16;
    }
#pragma unroll
    for (int nf = 0; nf < 4; nf++) {
        const int row = wn * 32 + nf * 8 + (lane & 7);
        boff[nf] = row * GPITCH + ((lane >> 3) & 1) * 16;
    }

    issue(0, 0);
    CP_COMMIT();
    if (nchunks > 1) issue(1, 1);
    CP_COMMIT();

    for (int c = 0; c < nchunks; c++) {
        CP_WAIT1();
        __syncthreads();
        const uint32_t st = sb + (c & 1) * GSTAGE;
#pragma unroll
        for (int s = 0; s < 3; s++) {
            const uint32_t sA = st + ((s == 2) ? 1 : 0) * GTILE;
            const uint32_t sB = st + ((s == 1) ? 3 : 2) * GTILE;
#pragma unroll
            for (int ks = 0; ks < 2; ks++) {
                uint32_t a[4][4], b[4][2];
#pragma unroll
                for (int mf = 0; mf < 4; mf++)
                    LDSM_X4(a[mf][0], a[mf][1], a[mf][2], a[mf][3], sA + aoff[mf] + ks * 32);
#pragma unroll
                for (int nf = 0; nf < 4; nf++)
                    LDSM_X2(b[nf][0], b[nf][1], sB + boff[nf] + ks * 32);
#pragma unroll
                for (int mf = 0; mf < 4; mf++)
#pragma unroll
                    for (int nf = 0; nf < 4; nf++)
                        MMA16816(acc[mf][nf], a[mf], b[nf]);
            }
        }
        __syncthreads();
        if (c + 2 < nchunks) issue(c & 1, c + 2);
        CP_COMMIT();
    }

    // epilogue
    const int lm = lane >> 2, ln = (lane & 3) * 2;
#pragma unroll
    for (int mf = 0; mf < 4; mf++) {
#pragma unroll
        for (int nf = 0; nf < 4; nf++) {
            const int n = bn + wn * 32 + nf * 8 + ln;
            if (n < Nreal) {
                const int m = bm + wm * 64 + mf * 16 + lm;
                float* p0 = C + (size_t)m * ldC + n;
                float* p1 = C + (size_t)(m + 8) * ldC + n;
                p0[0] = acc[mf][nf][0]; p0[1] = acc[mf][nf][1];
                p1[0] = acc[mf][nf][2]; p1[1] = acc[mf][nf][3];
            }
        }
    }
}

// ======================= rmsnorm / rope ======================================
__global__ void rmsnorm_kernel(const float* __restrict__ x, int srcStride, int srcOff, int W,
                               const float* __restrict__ w, float* __restrict__ y) {
    const int row = blockIdx.x;
    const float* xr = x + (size_t)row * srcStride + srcOff;
    float ss = 0.f;
    for (int c = threadIdx.x; c < W; c += blockDim.x) {
        float v = xr[c];
        ss += v * v;
    }
    __shared__ float red[32];
#pragma unroll
    for (int o = 16; o; o >>= 1) ss += __shfl_xor_sync(0xffffffffu, ss, o);
    if ((threadIdx.x & 31) == 0) red[threadIdx.x >> 5] = ss;
    __syncthreads();
    if (threadIdx.x < 32) {
        float v = (threadIdx.x < (blockDim.x >> 5)) ? red[threadIdx.x] : 0.f;
#pragma unroll
        for (int o = 16; o; o >>= 1) v += __shfl_xor_sync(0xffffffffu, v, o);
        red[threadIdx.x] = v;
    }
    __syncthreads();
    const float rstd = rsqrtf(red[0] / (float)W + 1e-6f);
    float* yr = y + (size_t)row * W;
    for (int c = threadIdx.x; c < W; c += blockDim.x) yr[c] = xr[c] * rstd * w[c];
}

__global__ void rope_tab_kernel(const int* __restrict__ pos) {
    const int t = blockIdx.x, i = threadIdx.x;
    double inv = pow(10000.0, -(double)i / 32.0);
    double f = (double)pos[t] * inv;
    double s, c;
    sincos(f, &s, &c);
    g_cos[t * 32 + i] = (float)c;
    g_sin[t * 32 + i] = (float)s;
}

__global__ void rope_q_kernel() {
    const int h = blockIdx.x, t = blockIdx.y, i = threadIdx.x;
    const float c = g_cos[t * 32 + i];
    const float s = g_sin[t * 32 + i];
    float* base = g_q + ((size_t)t * NH_ + h) * DQK_ + DN_ + 2 * i;
    const float x1 = base[0], x2 = base[1];
    base[0] = x1 * c - x2 * s;
    base[1] = x2 * c + x1 * s;
}

__global__ void rope_k_kernel() {
    const int t = blockIdx.x, i = threadIdx.x;
    const float c = g_cos[t * 32 + i];
    const float s = g_sin[t * 32 + i];
    const float* src = g_qkv + (size_t)t * NQKV_ + (QLR_ + KVLR_) + 2 * i;
    const float x1 = src[0], x2 = src[1];
    g_kpe[t * DR_ + 2 * i]     = x1 * c - x2 * s;
    g_kpe[t * DR_ + 2 * i + 1] = x2 * c + x1 * s;
}

// ======================= flash attention (fp32 SIMT) =========================
#define QB_ 64
#define KB_ 64

struct AttnSmem {
    float Q[QB_][DQK_ + 1];
    float K[KB_][DQK_ + 1];
    float V[KB_][DV_];
    float P[QB_][KB_ + 1];
    float rowM[QB_], rowL[QB_], rowScale[QB_];
};

__global__ void attn_kernel() {
    extern __shared__ char smem_raw[];
    AttnSmem& sm = *(AttnSmem*)smem_raw;
    const int h = blockIdx.x;
    const int qb = blockIdx.y;
    const int tid = threadIdx.x;
    const int tx = tid & 15, ty = tid >> 4;
    const int r0 = ty * 4;
    const int c0 = tx * 4;
    const int c0v = tx * 8;

    for (int idx = tid; idx < QB_ * DQK_; idx += 256) {
        int r = idx / DQK_, c = idx % DQK_;
        sm.Q[r][c] = g_q[((size_t)(qb * QB_ + r) * NH_ + h) * DQK_ + c];
    }
    if (tid < QB_) {
        sm.rowM[tid] = -1e30f;
        sm.rowL[tid] = 0.f;
    }
    float o[4][8];
#pragma unroll
    for (int i = 0; i < 4; i++)
#pragma unroll
        for (int j = 0; j < 8; j++) o[i][j] = 0.f;
    __syncthreads();

    const float scaling = rsqrtf((float)DQK_);

    for (int kc = 0; kc <= qb; kc++) {
        for (int idx = tid; idx < KB_ * DQK_; idx += 256) {
            int r = idx / DQK_, c = idx % DQK_;
            int tk = kc * KB_ + r;
            sm.K[r][c] = (c < DN_) ? g_kv[((size_t)tk * NH_ + h) * DKV_ + c]
                                   : g_kpe[tk * DR_ + (c - DN_)];
        }
        for (int idx = tid; idx < KB_ * DV_; idx += 256) {
            int r = idx / DV_, c = idx % DV_;
            int tk = kc * KB_ + r;
            sm.V[r][c] = g_kv[((size_t)tk * NH_ + h) * DKV_ + DN_ + c];
        }
        __syncthreads();

        float s4[4][4];
#pragma unroll
        for (int i = 0; i < 4; i++)
#pragma unroll
            for (int j = 0; j < 4; j++) s4[i][j] = 0.f;
#pragma unroll 4
        for (int k = 0; k < DQK_; k++) {
            float a0 = sm.Q[r0][k], a1 = sm.Q[r0 + 1][k], a2 = sm.Q[r0 + 2][k], a3 = sm.Q[r0 + 3][k];
            float b0 = sm.K[c0][k], b1 = sm.K[c0 + 1][k], b2 = sm.K[c0 + 2][k], b3 = sm.K[c0 + 3][k];
            s4[0][0] = fmaf(a0, b0, s4[0][0]); s4[0][1] = fmaf(a0, b1, s4[0][1]);
            s4[0][2] = fmaf(a0, b2, s4[0][2]); s4[0][3] = fmaf(a0, b3, s4[0][3]);
            s4[1][0] = fmaf(a1, b0, s4[1][0]); s4[1][1] = fmaf(a1, b1, s4[1][1]);
            s4[1][2] = fmaf(a1, b2, s4[1][2]); s4[1][3] = fmaf(a1, b3, s4[1][3]);
            s4[2][0] = fmaf(a2, b0, s4[2][0]); s4[2][1] = fmaf(a2, b1, s4[2][1]);
            s4[2][2] = fmaf(a2, b2, s4[2][2]); s4[2][3] = fmaf(a2, b3, s4[2][3]);
            s4[3][0] = fmaf(a3, b0, s4[3][0]); s4[3][1] = fmaf(a3, b1, s4[3][1]);
            s4[3][2] = fmaf(a3, b2, s4[3][2]); s4[3][3] = fmaf(a3, b3, s4[3][3]);
        }
        const bool diag = (kc == qb);
#pragma unroll
        for (int i = 0; i < 4; i++)
#pragma unroll
            for (int j = 0; j < 4; j++) {
                int rg = qb * QB_ + r0 + i, cg = kc * KB_ + c0 + j;
                float v = s4[i][j] * scaling;
                if (diag && cg > rg) v = -1e30f;
                sm.P[r0 + i][c0 + j] = v;
            }
        __syncthreads();

        {
            const int row = tid >> 2, lane = tid & 3;
            float mloc = -1e30f;
#pragma unroll
            for (int c = 0; c < 16; c++) mloc = fmaxf(mloc, sm.P[row][lane * 16 + c]);
            mloc = fmaxf(mloc, __shfl_xor_sync(0xffffffffu, mloc, 1));
            mloc = fmaxf(mloc, __shfl_xor_sync(0xffffffffu, mloc, 2));
            const float mprev = sm.rowM[row];
            const float mnew = fmaxf(mprev, mloc);
            float lsum = 0.f;
#pragma unroll
            for (int c = 0; c < 16; c++) {
                float p = __expf(sm.P[row][lane * 16 + c] - mnew);
                sm.P[row][lane * 16 + c] = p;
                lsum += p;
            }
            lsum += __shfl_xor_sync(0xffffffffu, lsum, 1);
            lsum += __shfl_xor_sync(0xffffffffu, lsum, 2);
            if (lane == 0) {
                float sc = __expf(mprev - mnew);
                sm.rowScale[row] = sc;
                sm.rowM[row] = mnew;
                sm.rowL[row] = sm.rowL[row] * sc + lsum;
            }
        }
        __syncthreads();

#pragma unroll
        for (int i = 0; i < 4; i++) {
            const float sc = sm.rowScale[r0 + i];
#pragma unroll
            for (int j = 0; j < 8; j++) o[i][j] *= sc;
        }
#pragma unroll 2
        for (int kk = 0; kk < KB_; kk++) {
            const float p0 = sm.P[r0][kk], p1 = sm.P[r0 + 1][kk];
            const float p2 = sm.P[r0 + 2][kk], p3 = sm.P[r0 + 3][kk];
            const float4 va = *(const float4*)&sm.V[kk][c0v];
            const float4 vb = *(const float4*)&sm.V[kk][c0v + 4];
            o[0][0] = fmaf(p0, va.x, o[0][0]); o[0][1] = fmaf(p0, va.y, o[0][1]);
            o[0][2] = fmaf(p0, va.z, o[0][2]); o[0][3] = fmaf(p0, va.w, o[0][3]);
            o[0][4] = fmaf(p0, vb.x, o[0][4]); o[0][5] = fmaf(p0, vb.y, o[0][5]);
            o[0][6] = fmaf(p0, vb.z, o[0][6]); o[0][7] = fmaf(p0, vb.w, o[0][7]);
            o[1][0] = fmaf(p1, va.x, o[1][0]); o[1][1] = fmaf(p1, va.y, o[1][1]);
            o[1][2] = fmaf(p1, va.z, o[1][2]); o[1][3] = fmaf(p1, va.w, o[1][3]);
            o[1][4] = fmaf(p1, vb.x, o[1][4]); o[1][5] = fmaf(p1, vb.y, o[1][5]);
            o[1][6] = fmaf(p1, vb.z, o[1][6]); o[1][7] = fmaf(p1, vb.w, o[1][7]);
            o[2][0] = fmaf(p2, va.x, o[2][0]); o[2][1] = fmaf(p2, va.y, o[2][1]);
            o[2][2] = fmaf(p2, va.z, o[2][2]); o[2][3] = fmaf(p2, va.w, o[2][3]);
            o[2][4] = fmaf(p2, vb.x, o[2][4]); o[2][5] = fmaf(p2, vb.y, o[2][5]);
            o[2][6] = fmaf(p2, vb.z, o[2][6]); o[2][7] = fmaf(p2, vb.w, o[2][7]);
            o[3][0] = fmaf(p3, va.x, o[3][0]); o[3][1] = fmaf(p3, va.y, o[3][1]);
            o[3][2] = fmaf(p3, va.z, o[3][2]); o[3][3] = fmaf(p3, va.w, o[3][3]);
            o[3][4] = fmaf(p3, vb.x, o[3][4]); o[3][5] = fmaf(p3, vb.y, o[3][5]);
            o[3][6] = fmaf(p3, vb.z, o[3][6]); o[3][7] = fmaf(p3, vb.w, o[3][7]);
        }
        __syncthreads();
    }

#pragma unroll
    for (int i = 0; i < 4; i++) {
        const float inv = 1.f / sm.rowL[r0 + i];
        float* dst = g_attn + (size_t)(qb * QB_ + r0 + i) * (NH_ * DV_) + h * DV_ + c0v;
#pragma unroll
        for (int j = 0; j < 8; j++) dst[j] = o[i][j] * inv;
    }
}

// ======================= launch ==============================================
extern "C" void kernel_launch(void* const* d_in, const int* in_sizes, int n_in,
                              void* d_out, int out_size) {
    const int*   positions = (const int*)d_in[0];
    const float* hidden    = (const float*)d_in[1];
    const float* w_qkv_a   = (const float*)d_in[2];
    const float* q_a_ln_w  = (const float*)d_in[3];
    const float* w_q_b     = (const float*)d_in[4];
    const float* kv_a_ln_w = (const float*)d_in[5];
    const float* w_kv_b    = (const float*)d_in[6];
    const float* w_o       = (const float*)d_in[7];
    float* out = (float*)d_out;

    float *p_qkv, *p_qan, *p_kvan, *p_q, *p_kv, *p_attn;
    cudaGetSymbolAddress((void**)&p_qkv,  g_qkv);
    cudaGetSymbolAddress((void**)&p_qan,  g_qan);
    cudaGetSymbolAddress((void**)&p_kvan, g_kvan);
    cudaGetSymbolAddress((void**)&p_q,    g_q);
    cudaGetSymbolAddress((void**)&p_kv,   g_kv);
    cudaGetSymbolAddress((void**)&p_attn, g_attn);

    __nv_bfloat16 *w1h, *w1l, *w2h, *w2l, *w3h, *w3l, *w4h, *w4l, *ah, *al;
    cudaGetSymbolAddress((void**)&w1h, g_w1h); cudaGetSymbolAddress((void**)&w1l, g_w1l);
    cudaGetSymbolAddress((void**)&w2h, g_w2h); cudaGetSymbolAddress((void**)&w2l, g_w2l);
    cudaGetSymbolAddress((void**)&w3h, g_w3h); cudaGetSymbolAddress((void**)&w3l, g_w3l);
    cudaGetSymbolAddress((void**)&w4h, g_w4h); cudaGetSymbolAddress((void**)&w4l, g_w4l);
    cudaGetSymbolAddress((void**)&ah,  g_ah);  cudaGetSymbolAddress((void**)&al,  g_al);

    cudaFuncSetAttribute(gemm_hmma, cudaFuncAttributeMaxDynamicSharedMemorySize, GEMM_SMEM);
    static const size_t attn_smem = sizeof(AttnSmem);
    cudaFuncSetAttribute(attn_kernel, cudaFuncAttributeMaxDynamicSharedMemorySize, (int)attn_smem);

    const dim3 cb(32, 8);

    // weight conversions (transpose + bf16 split; pad rows zeroed)
    convBT_kernel<<<dim3(HID_ / 32, NQKV_PAD_ / 32), cb>>>(w_qkv_a, w1h, w1l, HID_, NQKV_);
    convBT_kernel<<<dim3(QLR_ / 32, (NH_ * DQK_) / 32), cb>>>(w_q_b, w2h, w2l, QLR_, NH_ * DQK_);
    convBT_kernel<<<dim3(KVLR_ / 32, (NH_ * DKV_) / 32), cb>>>(w_kv_b, w3h, w3l, KVLR_, NH_ * DKV_);
    convBT_kernel<<<dim3((NH_ * DV_) / 32, HID_ / 32), cb>>>(w_o, w4h, w4l, NH_ * DV_, HID_);

    // GEMM1: qkv = hidden @ w_qkv_a   [1024,5120]x[5120,2112]
    convA_kernel<<<(T_ * HID_ + 255) / 256, 256>>>(hidden, ah, al, T_ * HID_);
    gemm_hmma<<<dim3(NQKV_PAD_ / 128, T_ / 128), 256, GEMM_SMEM>>>(ah, al, w1h, w1l, p_qkv, NQKV_, NQKV_, HID_);

    rmsnorm_kernel<<<T_, 256>>>(p_qkv, NQKV_, 0,    QLR_,  q_a_ln_w,  p_qan);
    rmsnorm_kernel<<<T_, 256>>>(p_qkv, NQKV_, QLR_, KVLR_, kv_a_ln_w, p_kvan);

    // GEMM2: q = q_a_n @ w_q_b   [1024,1536]x[1536,24576]
    convA_kernel<<<(T_ * QLR_ + 255) / 256, 256>>>(p_qan, ah, al, T_ * QLR_);
    gemm_hmma<<<dim3((NH_ * DQK_) / 128, T_ / 128), 256, GEMM_SMEM>>>(ah, al, w2h, w2l, p_q, NH_ * DQK_, NH_ * DQK_, QLR_);

    // GEMM3: kv = kv_a_n @ w_kv_b [1024,512]x[512,32768]
    convA_kernel<<<(T_ * KVLR_ + 255) / 256, 256>>>(p_kvan, ah, al, T_ * KVLR_);
    gemm_hmma<<<dim3((NH_ * DKV_) / 128, T_ / 128), 256, GEMM_SMEM>>>(ah, al, w3h, w3l, p_kv, NH_ * DKV_, NH_ * DKV_, KVLR_);

    // RoPE
    rope_tab_kernel<<<T_, 32>>>(positions);
    rope_q_kernel<<<dim3(NH_, T_), 32>>>();
    rope_k_kernel<<<T_, 32>>>();

    // attention (fp32 SIMT)
    attn_kernel<<<dim3(NH_, T_ / QB_), 256, attn_smem>>>();

    // GEMM4: out = attn @ w_o  [1024,16384]x[16384,5120]
    convA_kernel<<<(T_ * NH_ * DV_ + 255) / 256, 256>>>(p_attn, ah, al, T_ * NH_ * DV_);
    gemm_hmma<<<dim3(HID_ / 128, T_ / 128), 256, GEMM_SMEM>>>(ah, al, w4h, w4l, out, HID_, HID_, NH_ * DV_);
}

// round 4
// speedup vs baseline: 3.1718x; 1.5618x over previous
#include <cuda_runtime.h>
#include <cuda_bf16.h>
#include <math.h>
#include <stdint.h>

#define T_   1024
#define HID_ 5120
#define NH_  128
#define DN_  128
#define DR_  64
#define DV_  128
#define QLR_ 1536
#define KVLR_ 512
#define DQK_ 192    // DN+DR
#define DKV_ 256    // DN+DV
#define NQKV_ 2112  // QLR+KVLR+DR
#define NQKV_PAD_ 2304

// ---------------- fp32 scratch ----------------------------------------------
__device__ float g_qkv [T_ * NQKV_];
__device__ float g_q   [T_ * NH_ * DQK_];
__device__ float g_kv  [T_ * NH_ * DKV_];
__device__ float g_kpe [T_ * DR_];
__device__ float g_cos [T_ * 32];
__device__ float g_sin [T_ * 32];

// ---------------- bf16 split scratch ----------------------------------------
__device__ __nv_bfloat16 g_w1h[NQKV_PAD_ * HID_];
__device__ __nv_bfloat16 g_w1l[NQKV_PAD_ * HID_];
__device__ __nv_bfloat16 g_w2h[(NH_*DQK_) * QLR_];
__device__ __nv_bfloat16 g_w2l[(NH_*DQK_) * QLR_];
__device__ __nv_bfloat16 g_w3h[(NH_*DKV_) * KVLR_];
__device__ __nv_bfloat16 g_w3l[(NH_*DKV_) * KVLR_];
__device__ __nv_bfloat16 g_w4h[HID_ * (NH_*DV_)];
__device__ __nv_bfloat16 g_w4l[HID_ * (NH_*DV_)];
__device__ __nv_bfloat16 g_ah [T_ * (NH_*DV_)];      // A buf: hidden conv, then attn out
__device__ __nv_bfloat16 g_al [T_ * (NH_*DV_)];
__device__ __nv_bfloat16 g_qanh[T_ * QLR_], g_qanl[T_ * QLR_];
__device__ __nv_bfloat16 g_kvanh[T_ * KVLR_], g_kvanl[T_ * KVLR_];
__device__ __nv_bfloat16 g_qh[T_ * NH_ * DQK_], g_ql[T_ * NH_ * DQK_];
__device__ __nv_bfloat16 g_kh[T_ * NH_ * DQK_], g_kl[T_ * NH_ * DQK_];
__device__ __nv_bfloat16 g_vth[NH_ * DV_ * T_], g_vtl[NH_ * DV_ * T_];  // [h][d][t]

// ======================= PTX helpers =========================================
__device__ __forceinline__ uint32_t smem_u32(const void* p) {
    uint32_t a;
    asm("{ .reg .u64 t; cvta.to.shared.u64 t, %1; cvt.u32.u64 %0, t; }" : "=r"(a) : "l"(p));
    return a;
}

#define CP_ASYNC16(dst_u32, src_ptr) \
    asm volatile("cp.async.cg.shared.global [%0], [%1], 16;" :: "r"(dst_u32), "l"(src_ptr))
#define CP_COMMIT() asm volatile("cp.async.commit_group;" ::: "memory")
#define CP_WAIT1()  asm volatile("cp.async.wait_group 1;" ::: "memory")
#define CP_WAIT0()  asm volatile("cp.async.wait_group 0;" ::: "memory")

#define LDSM_X4(r0, r1, r2, r3, addr) \
    asm volatile("ldmatrix.sync.aligned.m8n8.x4.shared.b16 {%0,%1,%2,%3}, [%4];" \
        : "=r"(r0), "=r"(r1), "=r"(r2), "=r"(r3) : "r"(addr))
#define LDSM_X2(r0, r1, addr) \
    asm volatile("ldmatrix.sync.aligned.m8n8.x2.shared.b16 {%0,%1}, [%2];" \
        : "=r"(r0), "=r"(r1) : "r"(addr))

#define MMA16816(d, a, b) \
    asm volatile("mma.sync.aligned.m16n8k16.row.col.f32.bf16.bf16.f32 " \
        "{%0,%1,%2,%3},{%4,%5,%6,%7},{%8,%9},{%0,%1,%2,%3};" \
        : "+f"((d)[0]), "+f"((d)[1]), "+f"((d)[2]), "+f"((d)[3]) \
        : "r"((a)[0]), "r"((a)[1]), "r"((a)[2]), "r"((a)[3]), "r"((b)[0]), "r"((b)[1]))

// ======================= bf16 split conversion ===============================
__device__ __forceinline__ void split2(float v, __nv_bfloat16& h, __nv_bfloat16& l) {
    h = __float2bfloat16_rn(v);
    l = __float2bfloat16_rn(v - __bfloat162float(h));
}

__global__ void convA_kernel(const float* __restrict__ A,
                             __nv_bfloat16* __restrict__ H,
                             __nv_bfloat16* __restrict__ L, int n) {
    int i = blockIdx.x * blockDim.x + threadIdx.x;
    if (i < n) {
        __nv_bfloat16 h, l;
        split2(A[i], h, l);
        H[i] = h; L[i] = l;
    }
}

__global__ void convBT_kernel(const float* __restrict__ B,
                              __nv_bfloat16* __restrict__ TH,
                              __nv_bfloat16* __restrict__ TL,
                              int K, int N) {
    __shared__ float tile[32][33];
    const int k0 = blockIdx.x * 32, n0 = blockIdx.y * 32;
    const int tx = threadIdx.x, ty = threadIdx.y; // 32 x 8
    for (int i = ty; i < 32; i += 8) {
        int n = n0 + tx;
        tile[i][tx] = (n < N) ? B[(size_t)(k0 + i) * N + n] : 0.f;
    }
    __syncthreads();
    for (int i = ty; i < 32; i += 8) {
        float v = tile[tx][i];
        __nv_bfloat16 h, l;
        split2(v, h, l);
        size_t off = (size_t)(n0 + i) * K + k0 + tx;
        TH[off] = h; TL[off] = l;
    }
}

// ======================= HMMA split GEMM (proven) ============================
#define GPITCH 80
#define GTILE  (128 * GPITCH)
#define GSTAGE (4 * GTILE)
#define GEMM_SMEM (2 * GSTAGE)

__global__ void __launch_bounds__(256, 2)
gemm_hmma(const __nv_bfloat16* __restrict__ Ah, const __nv_bfloat16* __restrict__ Al,
          const __nv_bfloat16* __restrict__ Bh, const __nv_bfloat16* __restrict__ Bl,
          float* __restrict__ C, int Nreal, int ldC, int K) {
    extern __shared__ char smem[];
    const uint32_t sb = smem_u32(smem);
    const int tid  = threadIdx.x;
    const int wid  = tid >> 5;
    const int lane = tid & 31;
    const int wm   = wid & 1;
    const int wn   = wid >> 1;
    const int bm   = blockIdx.y * 128;
    const int bn   = blockIdx.x * 128;
    const int nchunks = K >> 5;

    const int r0c = tid >> 2, c40 = (tid & 3);

    auto issue = [&](int stage, int c) {
        const int k0 = c << 5;
        const uint32_t st = sb + stage * GSTAGE;
#pragma unroll
        for (int p = 0; p < 2; p++) {
            const int row = r0c + p * 64;
            const uint32_t doff = row * GPITCH + c40 * 16;
            const size_t goA = (size_t)(bm + row) * K + k0 + c40 * 8;
            const size_t goB = (size_t)(bn + row) * K + k0 + c40 * 8;
            CP_ASYNC16(st + 0 * GTILE + doff, Ah + goA);
            CP_ASYNC16(st + 1 * GTILE + doff, Al + goA);
            CP_ASYNC16(st + 2 * GTILE + doff, Bh + goB);
            CP_ASYNC16(st + 3 * GTILE + doff, Bl + goB);
        }
    };

    float acc[4][4][4];
#pragma unroll
    for (int i = 0; i < 4; i++)
#pragma unroll
        for (int j = 0; j < 4; j++)
#pragma unroll
            for (int q = 0; q < 4; q++) acc[i][j][q] = 0.f;

    uint32_t aoff[4], boff[4];
#pragma unroll
    for (int mf = 0; mf < 4; mf++) {
        const int row = wm * 64 + mf * 16 + (lane & 15);
        aoff[mf] = row * GPITCH + ((lane >> 4) & 1) * 16;
    }
#pragma unroll
    for (int nf = 0; nf < 4; nf++) {
        const int row = wn * 32 + nf * 8 + (lane & 7);
        boff[nf] = row * GPITCH + ((lane >> 3) & 1) * 16;
    }

    issue(0, 0);
    CP_COMMIT();
    if (nchunks > 1) issue(1, 1);
    CP_COMMIT();

    for (int c = 0; c < nchunks; c++) {
        CP_WAIT1();
        __syncthreads();
        const uint32_t st = sb + (c & 1) * GSTAGE;
#pragma unroll
        for (int s = 0; s < 3; s++) {
            const uint32_t sA = st + ((s == 2) ? 1 : 0) * GTILE;
            const uint32_t sB = st + ((s == 1) ? 3 : 2) * GTILE;
#pragma unroll
            for (int ks = 0; ks < 2; ks++) {
                uint32_t a[4][4], b[4][2];
#pragma unroll
                for (int mf = 0; mf < 4; mf++)
                    LDSM_X4(a[mf][0], a[mf][1], a[mf][2], a[mf][3], sA + aoff[mf] + ks * 32);
#pragma unroll
                for (int nf = 0; nf < 4; nf++)
                    LDSM_X2(b[nf][0], b[nf][1], sB + boff[nf] + ks * 32);
#pragma unroll
                for (int mf = 0; mf < 4; mf++)
#pragma unroll
                    for (int nf = 0; nf < 4; nf++)
                        MMA16816(acc[mf][nf], a[mf], b[nf]);
            }
        }
        __syncthreads();
        if (c + 2 < nchunks) issue(c & 1, c + 2);
        CP_COMMIT();
    }

    const int lm = lane >> 2, ln = (lane & 3) * 2;
#pragma unroll
    for (int mf = 0; mf < 4; mf++) {
#pragma unroll
        for (int nf = 0; nf < 4; nf++) {
            const int n = bn + wn * 32 + nf * 8 + ln;
            if (n < Nreal) {
                const int m = bm + wm * 64 + mf * 16 + lm;
                float* p0 = C + (size_t)m * ldC + n;
                float* p1 = C + (size_t)(m + 8) * ldC + n;
                p0[0] = acc[mf][nf][0]; p0[1] = acc[mf][nf][1];
                p1[0] = acc[mf][nf][2]; p1[1] = acc[mf][nf][3];
            }
        }
    }
}

// ======================= rmsnorm (split bf16 output) =========================
__global__ void rmsnorm_split(const float* __restrict__ x, int srcStride, int srcOff, int W,
                              const float* __restrict__ w,
                              __nv_bfloat16* __restrict__ H, __nv_bfloat16* __restrict__ L) {
    const int row = blockIdx.x;
    const float* xr = x + (size_t)row * srcStride + srcOff;
    float ss = 0.f;
    for (int c = threadIdx.x; c < W; c += blockDim.x) {
        float v = xr[c];
        ss += v * v;
    }
    __shared__ float red[32];
#pragma unroll
    for (int o = 16; o; o >>= 1) ss += __shfl_xor_sync(0xffffffffu, ss, o);
    if ((threadIdx.x & 31) == 0) red[threadIdx.x >> 5] = ss;
    __syncthreads();
    if (threadIdx.x < 32) {
        float v = (threadIdx.x < (blockDim.x >> 5)) ? red[threadIdx.x] : 0.f;
#pragma unroll
        for (int o = 16; o; o >>= 1) v += __shfl_xor_sync(0xffffffffu, v, o);
        red[threadIdx.x] = v;
    }
    __syncthreads();
    const float rstd = rsqrtf(red[0] / (float)W + 1e-6f);
    for (int c = threadIdx.x; c < W; c += blockDim.x) {
        __nv_bfloat16 hh, ll;
        split2(xr[c] * rstd * w[c], hh, ll);
        H[(size_t)row * W + c] = hh;
        L[(size_t)row * W + c] = ll;
    }
}

// ======================= RoPE ================================================
__global__ void rope_tab_kernel(const int* __restrict__ pos) {
    const int t = blockIdx.x, i = threadIdx.x;
    double inv = pow(10000.0, -(double)i / 32.0);
    double f = (double)pos[t] * inv;
    double s, c;
    sincos(f, &s, &c);
    g_cos[t * 32 + i] = (float)c;
    g_sin[t * 32 + i] = (float)s;
}

__global__ void rope_k_kernel() {
    const int t = blockIdx.x, i = threadIdx.x;
    const float c = g_cos[t * 32 + i];
    const float s = g_sin[t * 32 + i];
    const float* src = g_qkv + (size_t)t * NQKV_ + (QLR_ + KVLR_) + 2 * i;
    const float x1 = src[0], x2 = src[1];
    g_kpe[t * DR_ + 2 * i]     = x1 * c - x2 * s;
    g_kpe[t * DR_ + 2 * i + 1] = x2 * c + x1 * s;
}

// q build: rope (last 64) + scaling + split -> g_qh/g_ql  [t][h][192]
__global__ void qbuild_kernel() {
    const int t = blockIdx.y, h = blockIdx.x * 4 + threadIdx.y;
    const int i = threadIdx.x; // 0..95, elems 2i, 2i+1
    const float scaling = rsqrtf((float)DQK_);
    const size_t base = ((size_t)t * NH_ + h) * DQK_ + 2 * i;
    float x1 = g_q[base], x2 = g_q[base + 1];
    if (i >= 64) {
        const int j = i - 64;
        const float c = g_cos[t * 32 + j], s = g_sin[t * 32 + j];
        const float o1 = x1 * c - x2 * s, o2 = x2 * c + x1 * s;
        x1 = o1; x2 = o2;
    }
    x1 *= scaling; x2 *= scaling;
    __nv_bfloat16 hh, ll;
    split2(x1, hh, ll); g_qh[base] = hh; g_ql[base] = ll;
    split2(x2, hh, ll); g_qh[base + 1] = hh; g_ql[base + 1] = ll;
}

// k build: concat(kv nope, roped kpe) + split -> g_kh/g_kl  [t][h][192]
__global__ void kbuild_kernel() {
    const int t = blockIdx.y, h = blockIdx.x * 4 + threadIdx.y;
    const int i = threadIdx.x; // 0..95
    float x1, x2;
    if (i < 64) {
        const size_t s = ((size_t)t * NH_ + h) * DKV_ + 2 * i;
        x1 = g_kv[s]; x2 = g_kv[s + 1];
    } else {
        const int j = 2 * (i - 64);
        x1 = g_kpe[t * DR_ + j]; x2 = g_kpe[t * DR_ + j + 1];
    }
    const size_t d = ((size_t)t * NH_ + h) * DQK_ + 2 * i;
    __nv_bfloat16 hh, ll;
    split2(x1, hh, ll); g_kh[d] = hh; g_kl[d] = ll;
    split2(x2, hh, ll); g_kh[d + 1] = hh; g_kl[d + 1] = ll;
}

// v transpose + split: g_kv v-part [t][h][128] -> g_vth/g_vtl [h][d][t]
__global__ void vtrans_kernel() {
    __shared__ float tile[32][33];
    const int t0 = blockIdx.x * 32, d0 = blockIdx.y * 32, h = blockIdx.z;
    const int tx = threadIdx.x, ty = threadIdx.y; // 32 x 8
    for (int i = ty; i < 32; i += 8)
        tile[i][tx] = g_kv[((size_t)(t0 + i) * NH_ + h) * DKV_ + DN_ + d0 + tx];
    __syncthreads();
    for (int i = ty; i < 32; i += 8) {
        __nv_bfloat16 hh, ll;
        split2(tile[tx][i], hh, ll);
        const size_t off = ((size_t)h * DV_ + d0 + i) * T_ + t0 + tx;
        g_vth[off] = hh; g_vtl[off] = ll;
    }
}

// ======================= HMMA flash attention ================================
// CTA = (head, 64-row q block). 8 warps: S warp grid 4m x 2n (16x32 tiles),
// O warp grid 4m x 2n (16x64 tiles). 3-term bf16 split everywhere, fp32 softmax.
#define QKP 200   // Q/K smem pitch (elems): 400B, (400/16)%8=1 -> conflict-free
#define PVP 72    // P/Vt pitch: 144B, (144/16)%8=1 -> conflict-free
#define SFP 68

struct ASmem {
    __nv_bfloat16 Qh[64 * QKP], Ql[64 * QKP];
    __nv_bfloat16 Kh[64 * QKP], Kl[64 * QKP];
    __nv_bfloat16 Vh[128 * PVP], Vl[128 * PVP];
    __nv_bfloat16 Ph[64 * PVP], Pl[64 * PVP];
    float Sf[64 * SFP];
    float rowM[64], rowL[64], rowScale[64];
};
#define ATTN_SMEM sizeof(ASmem)

__global__ void __launch_bounds__(256, 1)
attn_mma() {
    extern __shared__ char smem_raw[];
    ASmem& sm = *(ASmem*)smem_raw;
    const int h = blockIdx.x, qb = blockIdx.y;
    const int tid = threadIdx.x, wid = tid >> 5, lane = tid & 31;
    const int wm = wid & 3, wn = wid >> 2;
    const int t0 = qb * 64;
    const int lm = lane >> 2, ln = (lane & 3) * 2;

    const uint32_t sQh = smem_u32(sm.Qh), sQl = smem_u32(sm.Ql);
    const uint32_t sKh = smem_u32(sm.Kh), sKl = smem_u32(sm.Kl);
    const uint32_t sVh = smem_u32(sm.Vh), sVl = smem_u32(sm.Vl);
    const uint32_t sPh = smem_u32(sm.Ph), sPl = smem_u32(sm.Pl);

    // ---- load Q (64 rows x 192 elems, hi+lo) via cp.async ----
    for (int idx = tid; idx < 64 * 24; idx += 256) {
        const int row = idx / 24, ch = idx % 24;
        const size_t go = ((size_t)(t0 + row) * NH_ + h) * DQK_ + ch * 8;
        const uint32_t so = (row * QKP + ch * 8) * 2;
        CP_ASYNC16(sQh + so, g_qh + go);
        CP_ASYNC16(sQl + so, g_ql + go);
    }
    CP_COMMIT();
    if (tid < 64) {
        sm.rowM[tid] = -1e30f;
        sm.rowL[tid] = 0.f;
    }

    // ldmatrix offsets
    const uint32_t aoffQ = ((wm * 16 + (lane & 15)) * QKP + ((lane >> 4) & 1) * 8) * 2;
    uint32_t boffK[4];
#pragma unroll
    for (int nf = 0; nf < 4; nf++)
        boffK[nf] = ((wn * 32 + nf * 8 + (lane & 7)) * QKP + ((lane >> 3) & 1) * 8) * 2;
    const uint32_t aoffP = ((wm * 16 + (lane & 15)) * PVP + ((lane >> 4) & 1) * 8) * 2;
    uint32_t boffV[8];
#pragma unroll
    for (int nf = 0; nf < 8; nf++)
        boffV[nf] = ((wn * 64 + nf * 8 + (lane & 7)) * PVP + ((lane >> 3) & 1) * 8) * 2;

    float accO[8][4];
#pragma unroll
    for (int i = 0; i < 8; i++)
#pragma unroll
        for (int q = 0; q < 4; q++) accO[i][q] = 0.f;

    for (int kc = 0; kc <= qb; kc++) {
        // ---- load K chunk + V chunk ----
        const int tk0 = kc * 64;
        for (int idx = tid; idx < 64 * 24; idx += 256) {
            const int row = idx / 24, ch = idx % 24;
            const size_t go = ((size_t)(tk0 + row) * NH_ + h) * DQK_ + ch * 8;
            const uint32_t so = (row * QKP + ch * 8) * 2;
            CP_ASYNC16(sKh + so, g_kh + go);
            CP_ASYNC16(sKl + so, g_kl + go);
        }
        for (int idx = tid; idx < 128 * 8; idx += 256) {
            const int row = idx >> 3, ch = idx & 7;
            const size_t go = ((size_t)h * DV_ + row) * T_ + tk0 + ch * 8;
            const uint32_t so = (row * PVP + ch * 8) * 2;
            CP_ASYNC16(sVh + so, g_vth + go);
            CP_ASYNC16(sVl + so, g_vtl + go);
        }
        CP_COMMIT();
        CP_WAIT0();
        __syncthreads();

        // ---- S = Q K^T (split, fp32 accum) ----
        float accS[4][4];
#pragma unroll
        for (int i = 0; i < 4; i++)
#pragma unroll
            for (int q = 0; q < 4; q++) accS[i][q] = 0.f;
#pragma unroll
        for (int ks = 0; ks < 12; ks++) {
            uint32_t ah[4], al[4];
            LDSM_X4(ah[0], ah[1], ah[2], ah[3], sQh + aoffQ + ks * 32);
            LDSM_X4(al[0], al[1], al[2], al[3], sQl + aoffQ + ks * 32);
#pragma unroll
            for (int nf = 0; nf < 4; nf++) {
                uint32_t bh[2], bl[2];
                LDSM_X2(bh[0], bh[1], sKh + boffK[nf] + ks * 32);
                LDSM_X2(bl[0], bl[1], sKl + boffK[nf] + ks * 32);
                MMA16816(accS[nf], ah, bh);
                MMA16816(accS[nf], ah, bl);
                MMA16816(accS[nf], al, bh);
            }
        }
        // write S (mask on diagonal chunk)
        const bool diag = (kc == qb);
#pragma unroll
        for (int nf = 0; nf < 4; nf++) {
            const int r = wm * 16 + lm;
            const int c = wn * 32 + nf * 8 + ln;
            float v0 = accS[nf][0], v1 = accS[nf][1], v2 = accS[nf][2], v3 = accS[nf][3];
            if (diag) {
                const int rg0 = t0 + r, rg1 = rg0 + 8, cg = tk0 + c;
                if (cg > rg0) v0 = -1e30f;
                if (cg + 1 > rg0) v1 = -1e30f;
                if (cg > rg1) v2 = -1e30f;
                if (cg + 1 > rg1) v3 = -1e30f;
            }
            sm.Sf[r * SFP + c] = v0;
            sm.Sf[r * SFP + c + 1] = v1;
            sm.Sf[(r + 8) * SFP + c] = v2;
            sm.Sf[(r + 8) * SFP + c + 1] = v3;
        }
        __syncthreads();

        // ---- online softmax: 4 threads per row over 64 cols ----
        {
            const int row = tid >> 2, l4 = tid & 3;
            float mloc = -1e30f;
#pragma unroll
            for (int c = 0; c < 16; c++) mloc = fmaxf(mloc, sm.Sf[row * SFP + l4 * 16 + c]);
            mloc = fmaxf(mloc, __shfl_xor_sync(0xffffffffu, mloc, 1));
            mloc = fmaxf(mloc, __shfl_xor_sync(0xffffffffu, mloc, 2));
            const float mprev = sm.rowM[row];
            const float mnew = fmaxf(mprev, mloc);
            float lsum = 0.f;
#pragma unroll
            for (int c = 0; c < 16; c++) {
                const int col = l4 * 16 + c;
                const float p = __expf(sm.Sf[row * SFP + col] - mnew);
                lsum += p;
                __nv_bfloat16 hh, ll;
                split2(p, hh, ll);
                sm.Ph[row * PVP + col] = hh;
                sm.Pl[row * PVP + col] = ll;
            }
            lsum += __shfl_xor_sync(0xffffffffu, lsum, 1);
            lsum += __shfl_xor_sync(0xffffffffu, lsum, 2);
            if (l4 == 0) {
                const float sc = __expf(mprev - mnew);
                sm.rowScale[row] = sc;
                sm.rowM[row] = mnew;
                sm.rowL[row] = sm.rowL[row] * sc + lsum;
            }
        }
        __syncthreads();

        // ---- rescale O, then O += P V (split) ----
        const float s0 = sm.rowScale[wm * 16 + lm];
        const float s1 = sm.rowScale[wm * 16 + lm + 8];
#pragma unroll
        for (int nf = 0; nf < 8; nf++) {
            accO[nf][0] *= s0; accO[nf][1] *= s0;
            accO[nf][2] *= s1; accO[nf][3] *= s1;
        }
#pragma unroll
        for (int ks = 0; ks < 4; ks++) {
            uint32_t pah[4], pal[4];
            LDSM_X4(pah[0], pah[1], pah[2], pah[3], sPh + aoffP + ks * 32);
            LDSM_X4(pal[0], pal[1], pal[2], pal[3], sPl + aoffP + ks * 32);
#pragma unroll
            for (int nf = 0; nf < 8; nf++) {
                uint32_t vbh[2], vbl[2];
                LDSM_X2(vbh[0], vbh[1], sVh + boffV[nf] + ks * 32);
                LDSM_X2(vbl[0], vbl[1], sVl + boffV[nf] + ks * 32);
                MMA16816(accO[nf], pah, vbh);
                MMA16816(accO[nf], pah, vbl);
                MMA16816(accO[nf], pal, vbh);
            }
        }
        __syncthreads();
    }

    // ---- finalize: /rowL, split -> g_ah/g_al  [t][h*128 + d] ----
    const float invL0 = 1.f / sm.rowL[wm * 16 + lm];
    const float invL1 = 1.f / sm.rowL[wm * 16 + lm + 8];
    const int r0g = t0 + wm * 16 + lm;
#pragma unroll
    for (int nf = 0; nf < 8; nf++) {
        const int col = h * DV_ + wn * 64 + nf * 8 + ln;
        __nv_bfloat16 h0, l0, h1, l1;
        split2(accO[nf][0] * invL0, h0, l0);
        split2(accO[nf][1] * invL0, h1, l1);
        *(__nv_bfloat162*)(g_ah + (size_t)r0g * (NH_ * DV_) + col) = __nv_bfloat162(h0, h1);
        *(__nv_bfloat162*)(g_al + (size_t)r0g * (NH_ * DV_) + col) = __nv_bfloat162(l0, l1);
        split2(accO[nf][2] * invL1, h0, l0);
        split2(accO[nf][3] * invL1, h1, l1);
        *(__nv_bfloat162*)(g_ah + (size_t)(r0g + 8) * (NH_ * DV_) + col) = __nv_bfloat162(h0, h1);
        *(__nv_bfloat162*)(g_al + (size_t)(r0g + 8) * (NH_ * DV_) + col) = __nv_bfloat162(l0, l1);
    }
}

// ======================= launch ==============================================
extern "C" void kernel_launch(void* const* d_in, const int* in_sizes, int n_in,
                              void* d_out, int out_size) {
    const int*   positions = (const int*)d_in[0];
    const float* hidden    = (const float*)d_in[1];
    const float* w_qkv_a   = (const float*)d_in[2];
    const float* q_a_ln_w  = (const float*)d_in[3];
    const float* w_q_b     = (const float*)d_in[4];
    const float* kv_a_ln_w = (const float*)d_in[5];
    const float* w_kv_b    = (const float*)d_in[6];
    const float* w_o       = (const float*)d_in[7];
    float* out = (float*)d_out;

    float *p_qkv, *p_q, *p_kv;
    cudaGetSymbolAddress((void**)&p_qkv, g_qkv);
    cudaGetSymbolAddress((void**)&p_q,   g_q);
    cudaGetSymbolAddress((void**)&p_kv,  g_kv);

    __nv_bfloat16 *w1h, *w1l, *w2h, *w2l, *w3h, *w3l, *w4h, *w4l, *ah, *al;
    __nv_bfloat16 *qanh, *qanl, *kvanh, *kvanl;
    cudaGetSymbolAddress((void**)&w1h, g_w1h); cudaGetSymbolAddress((void**)&w1l, g_w1l);
    cudaGetSymbolAddress((void**)&w2h, g_w2h); cudaGetSymbolAddress((void**)&w2l, g_w2l);
    cudaGetSymbolAddress((void**)&w3h, g_w3h); cudaGetSymbolAddress((void**)&w3l, g_w3l);
    cudaGetSymbolAddress((void**)&w4h, g_w4h); cudaGetSymbolAddress((void**)&w4l, g_w4l);
    cudaGetSymbolAddress((void**)&ah,  g_ah);  cudaGetSymbolAddress((void**)&al,  g_al);
    cudaGetSymbolAddress((void**)&qanh, g_qanh); cudaGetSymbolAddress((void**)&qanl, g_qanl);
    cudaGetSymbolAddress((void**)&kvanh, g_kvanh); cudaGetSymbolAddress((void**)&kvanl, g_kvanl);

    cudaFuncSetAttribute(gemm_hmma, cudaFuncAttributeMaxDynamicSharedMemorySize, GEMM_SMEM);
    cudaFuncSetAttribute(attn_mma, cudaFuncAttributeMaxDynamicSharedMemorySize, (int)ATTN_SMEM);

    const dim3 cb(32, 8);

    // weight conversions
    convBT_kernel<<<dim3(HID_ / 32, NQKV_PAD_ / 32), cb>>>(w_qkv_a, w1h, w1l, HID_, NQKV_);
    convBT_kernel<<<dim3(QLR_ / 32, (NH_ * DQK_) / 32), cb>>>(w_q_b, w2h, w2l, QLR_, NH_ * DQK_);
    convBT_kernel<<<dim3(KVLR_ / 32, (NH_ * DKV_) / 32), cb>>>(w_kv_b, w3h, w3l, KVLR_, NH_ * DKV_);
    convBT_kernel<<<dim3((NH_ * DV_) / 32, HID_ / 32), cb>>>(w_o, w4h, w4l, NH_ * DV_, HID_);

    // GEMM1: qkv = hidden @ w_qkv_a
    convA_kernel<<<(T_ * HID_ + 255) / 256, 256>>>(hidden, ah, al, T_ * HID_);
    gemm_hmma<<<dim3(NQKV_PAD_ / 128, T_ / 128), 256, GEMM_SMEM>>>(ah, al, w1h, w1l, p_qkv, NQKV_, NQKV_, HID_);

    // RoPE tables + k_pe (needs qkv)
    rope_tab_kernel<<<T_, 32>>>(positions);
    rope_k_kernel<<<T_, 32>>>();

    // rmsnorms -> split bf16
    rmsnorm_split<<<T_, 256>>>(p_qkv, NQKV_, 0,    QLR_,  q_a_ln_w,  qanh,  qanl);
    rmsnorm_split<<<T_, 256>>>(p_qkv, NQKV_, QLR_, KVLR_, kv_a_ln_w, kvanh, kvanl);

    // GEMM2 / GEMM3
    gemm_hmma<<<dim3((NH_ * DQK_) / 128, T_ / 128), 256, GEMM_SMEM>>>(qanh, qanl, w2h, w2l, p_q, NH_ * DQK_, NH_ * DQK_, QLR_);
    gemm_hmma<<<dim3((NH_ * DKV_) / 128, T_ / 128), 256, GEMM_SMEM>>>(kvanh, kvanl, w3h, w3l, p_kv, NH_ * DKV_, NH_ * DKV_, KVLR_);

    // build attention operands (bf16 splits)
    qbuild_kernel<<<dim3(NH_ / 4, T_), dim3(96, 4)>>>();
    kbuild_kernel<<<dim3(NH_ / 4, T_), dim3(96, 4)>>>();
    vtrans_kernel<<<dim3(T_ / 32, DV_ / 32, NH_), cb>>>();

    // attention -> g_ah/g_al (A operand of GEMM4)
    attn_mma<<<dim3(NH_, T_ / 64), 256, ATTN_SMEM>>>();

    // GEMM4: out = attn @ w_o
    gemm_hmma<<<dim3(HID_ / 128, T_ / 128), 256, GEMM_SMEM>>>(ah, al, w4h, w4l, out, HID_, HID_, NH_ * DV_);
}

// round 5
// speedup vs baseline: 3.5940x; 1.1331x over previous
#include <cuda_runtime.h>
#include <cuda_bf16.h>
#include <math.h>
#include <stdint.h>

#define T_   1024
#define HID_ 5120
#define NH_  128
#define DN_  128
#define DR_  64
#define DV_  128
#define QLR_ 1536
#define KVLR_ 512
#define DQK_ 192    // DN+DR
#define DKV_ 256    // DN+DV
#define NQKV_ 2112  // QLR+KVLR+DR
#define NQKV_PAD_ 2304

// ---------------- fp32 scratch ----------------------------------------------
__device__ float g_qkv [T_ * NQKV_];
__device__ float g_v   [T_ * NH_ * DV_];     // compact V from GEMM3 epilogue
__device__ float g_cos [T_ * 32];
__device__ float g_sin [T_ * 32];

// ---------------- bf16 split scratch ----------------------------------------
__device__ __nv_bfloat16 g_w1h[NQKV_PAD_ * HID_];
__device__ __nv_bfloat16 g_w1l[NQKV_PAD_ * HID_];
__device__ __nv_bfloat16 g_w2h[(NH_*DQK_) * QLR_];
__device__ __nv_bfloat16 g_w2l[(NH_*DQK_) * QLR_];
__device__ __nv_bfloat16 g_w3h[(NH_*DKV_) * KVLR_];
__device__ __nv_bfloat16 g_w3l[(NH_*DKV_) * KVLR_];
__device__ __nv_bfloat16 g_w4h[HID_ * (NH_*DV_)];
__device__ __nv_bfloat16 g_w4l[HID_ * (NH_*DV_)];
__device__ __nv_bfloat16 g_ah [T_ * (NH_*DV_)];      // A buf: hidden conv, then attn out
__device__ __nv_bfloat16 g_al [T_ * (NH_*DV_)];
__device__ __nv_bfloat16 g_qanh[T_ * QLR_], g_qanl[T_ * QLR_];
__device__ __nv_bfloat16 g_kvanh[T_ * KVLR_], g_kvanl[T_ * KVLR_];
__device__ __nv_bfloat16 g_qh[T_ * NH_ * DQK_], g_ql[T_ * NH_ * DQK_];
__device__ __nv_bfloat16 g_kh[T_ * NH_ * DQK_], g_kl[T_ * NH_ * DQK_];
__device__ __nv_bfloat16 g_vth[NH_ * DV_ * T_], g_vtl[NH_ * DV_ * T_];  // [h][d][t]

// ======================= PTX helpers =========================================
__device__ __forceinline__ uint32_t smem_u32(const void* p) {
    uint32_t a;
    asm("{ .reg .u64 t; cvta.to.shared.u64 t, %1; cvt.u32.u64 %0, t; }" : "=r"(a) : "l"(p));
    return a;
}

#define CP_ASYNC16(dst_u32, src_ptr) \
    asm volatile("cp.async.cg.shared.global [%0], [%1], 16;" :: "r"(dst_u32), "l"(src_ptr))
#define CP_COMMIT() asm volatile("cp.async.commit_group;" ::: "memory")
#define CP_WAIT1()  asm volatile("cp.async.wait_group 1;" ::: "memory")
#define CP_WAIT0()  asm volatile("cp.async.wait_group 0;" ::: "memory")

#define LDSM_X4(r0, r1, r2, r3, addr) \
    asm volatile("ldmatrix.sync.aligned.m8n8.x4.shared.b16 {%0,%1,%2,%3}, [%4];" \
        : "=r"(r0), "=r"(r1), "=r"(r2), "=r"(r3) : "r"(addr))
#define LDSM_X2(r0, r1, addr) \
    asm volatile("ldmatrix.sync.aligned.m8n8.x2.shared.b16 {%0,%1}, [%2];" \
        : "=r"(r0), "=r"(r1) : "r"(addr))

#define MMA16816(d, a, b) \
    asm volatile("mma.sync.aligned.m16n8k16.row.col.f32.bf16.bf16.f32 " \
        "{%0,%1,%2,%3},{%4,%5,%6,%7},{%8,%9},{%0,%1,%2,%3};" \
        : "+f"((d)[0]), "+f"((d)[1]), "+f"((d)[2]), "+f"((d)[3]) \
        : "r"((a)[0]), "r"((a)[1]), "r"((a)[2]), "r"((a)[3]), "r"((b)[0]), "r"((b)[1]))

// ======================= bf16 split conversion ===============================
__device__ __forceinline__ void split2(float v, __nv_bfloat16& h, __nv_bfloat16& l) {
    h = __float2bfloat16_rn(v);
    l = __float2bfloat16_rn(v - __bfloat162float(h));
}
__device__ __forceinline__ uint32_t pack2(__nv_bfloat16 a, __nv_bfloat16 b) {
    __nv_bfloat162 t(a, b);
    return *(uint32_t*)&t;
}

// vectorized elementwise split: 4 floats -> 4 bf16 hi + 4 bf16 lo
__global__ void convA4_kernel(const float* __restrict__ A,
                              __nv_bfloat16* __restrict__ H,
                              __nv_bfloat16* __restrict__ L, int n4) {
    int i = blockIdx.x * blockDim.x + threadIdx.x;
    if (i < n4) {
        float4 v = ((const float4*)A)[i];
        __nv_bfloat16 h0,l0,h1,l1,h2,l2,h3,l3;
        split2(v.x,h0,l0); split2(v.y,h1,l1); split2(v.z,h2,l2); split2(v.w,h3,l3);
        uint2 uh, ul;
        uh.x = pack2(h0,h1); uh.y = pack2(h2,h3);
        ul.x = pack2(l0,l1); ul.y = pack2(l2,l3);
        ((uint2*)H)[i] = uh; ((uint2*)L)[i] = ul;
    }
}

// B [K,N] fp32 -> Bt hi/lo [Npad,K] bf16 (transpose + split). 64x64 tiles,
// float4 reads, 8B packed writes. Requires K%4==0, N%4==0, Npad%64==0.
__global__ void convBT_kernel(const float* __restrict__ B,
                              __nv_bfloat16* __restrict__ TH,
                              __nv_bfloat16* __restrict__ TL,
                              int K, int N) {
    __shared__ float tile[64][65];
    const int k0 = blockIdx.x * 64, n0 = blockIdx.y * 64;
    const int tid = threadIdx.x; // 256
    for (int i = tid; i < 64 * 16; i += 256) {
        const int r = i >> 4, c4 = (i & 15) * 4;
        const int n = n0 + c4;
        float4 v = make_float4(0.f, 0.f, 0.f, 0.f);
        if (n < N) v = *(const float4*)(B + (size_t)(k0 + r) * N + n);
        tile[r][c4 + 0] = v.x; tile[r][c4 + 1] = v.y;
        tile[r][c4 + 2] = v.z; tile[r][c4 + 3] = v.w;
    }
    __syncthreads();
    for (int i = tid; i < 64 * 16; i += 256) {
        const int nr = i >> 4, kg = (i & 15) * 4;
        __nv_bfloat16 h0,l0,h1,l1,h2,l2,h3,l3;
        split2(tile[kg + 0][nr], h0, l0);
        split2(tile[kg + 1][nr], h1, l1);
        split2(tile[kg + 2][nr], h2, l2);
        split2(tile[kg + 3][nr], h3, l3);
        uint2 uh, ul;
        uh.x = pack2(h0,h1); uh.y = pack2(h2,h3);
        ul.x = pack2(l0,l1); ul.y = pack2(l2,l3);
        const size_t off = (size_t)(n0 + nr) * K + k0 + kg;
        *(uint2*)(TH + off) = uh;
        *(uint2*)(TL + off) = ul;
    }
}

// ======================= HMMA split GEMM with fused epilogues ================
// mode 0: C fp32 (guard n<Nreal)
// mode 1: q path  — scale by 1/sqrt(192), RoPE on d>=128, split -> outH/outL (ld = 24576)
// mode 2: kv path — d<128: split k-nope -> outH/outL [t][h*192+d]; d>=128: fp32 V -> vout
#define GPITCH 80
#define GTILE  (128 * GPITCH)
#define GSTAGE (4 * GTILE)
#define GEMM_SMEM (2 * GSTAGE)

__global__ void __launch_bounds__(256, 2)
gemm_hmma(const __nv_bfloat16* __restrict__ Ah, const __nv_bfloat16* __restrict__ Al,
          const __nv_bfloat16* __restrict__ Bh, const __nv_bfloat16* __restrict__ Bl,
          float* __restrict__ C, int Nreal, int ldC, int K, int mode,
          __nv_bfloat16* __restrict__ outH, __nv_bfloat16* __restrict__ outL,
          float* __restrict__ vout) {
    extern __shared__ char smem[];
    const uint32_t sb = smem_u32(smem);
    const int tid  = threadIdx.x;
    const int wid  = tid >> 5;
    const int lane = tid & 31;
    const int wm   = wid & 1;
    const int wn   = wid >> 1;
    const int bm   = blockIdx.y * 128;
    const int bn   = blockIdx.x * 128;
    const int nchunks = K >> 5;

    const int r0c = tid >> 2, c40 = (tid & 3);

    auto issue = [&](int stage, int c) {
        const int k0 = c << 5;
        const uint32_t st = sb + stage * GSTAGE;
#pragma unroll
        for (int p = 0; p < 2; p++) {
            const int row = r0c + p * 64;
            const uint32_t doff = row * GPITCH + c40 * 16;
            const size_t goA = (size_t)(bm + row) * K + k0 + c40 * 8;
            const size_t goB = (size_t)(bn + row) * K + k0 + c40 * 8;
            CP_ASYNC16(st + 0 * GTILE + doff, Ah + goA);
            CP_ASYNC16(st + 1 * GTILE + doff, Al + goA);
            CP_ASYNC16(st + 2 * GTILE + doff, Bh + goB);
            CP_ASYNC16(st + 3 * GTILE + doff, Bl + goB);
        }
    };

    float acc[4][4][4];
#pragma unroll
    for (int i = 0; i < 4; i++)
#pragma unroll
        for (int j = 0; j < 4; j++)
#pragma unroll
            for (int q = 0; q < 4; q++) acc[i][j][q] = 0.f;

    uint32_t aoff[4], boff[4];
#pragma unroll
    for (int mf = 0; mf < 4; mf++) {
        const int row = wm * 64 + mf * 16 + (lane & 15);
        aoff[mf] = row * GPITCH + ((lane >> 4) & 1) * 16;
    }
#pragma unroll
    for (int nf = 0; nf < 4; nf++) {
        const int row = wn * 32 + nf * 8 + (lane & 7);
        boff[nf] = row * GPITCH + ((lane >> 3) & 1) * 16;
    }

    issue(0, 0);
    CP_COMMIT();
    if (nchunks > 1) issue(1, 1);
    CP_COMMIT();

    for (int c = 0; c < nchunks; c++) {
        CP_WAIT1();
        __syncthreads();
        const uint32_t st = sb + (c & 1) * GSTAGE;
#pragma unroll
        for (int s = 0; s < 3; s++) {
            const uint32_t sA = st + ((s == 2) ? 1 : 0) * GTILE;
            const uint32_t sB = st + ((s == 1) ? 3 : 2) * GTILE;
#pragma unroll
            for (int ks = 0; ks < 2; ks++) {
                uint32_t a[4][4], b[4][2];
#pragma unroll
                for (int mf = 0; mf < 4; mf++)
                    LDSM_X4(a[mf][0], a[mf][1], a[mf][2], a[mf][3], sA + aoff[mf] + ks * 32);
#pragma unroll
                for (int nf = 0; nf < 4; nf++)
                    LDSM_X2(b[nf][0], b[nf][1], sB + boff[nf] + ks * 32);
#pragma unroll
                for (int mf = 0; mf < 4; mf++)
#pragma unroll
                    for (int nf = 0; nf < 4; nf++)
                        MMA16816(acc[mf][nf], a[mf], b[nf]);
            }
        }
        __syncthreads();
        if (c + 2 < nchunks) issue(c & 1, c + 2);
        CP_COMMIT();
    }

    const int lm = lane >> 2, ln = (lane & 3) * 2;
    const float qscale = 0.072168784f; // 1/sqrt(192)
#pragma unroll
    for (int mf = 0; mf < 4; mf++) {
#pragma unroll
        for (int nf = 0; nf < 4; nf++) {
            const int n = bn + wn * 32 + nf * 8 + ln;
            const int m = bm + wm * 64 + mf * 16 + lm;
            if (mode == 0) {
                if (n < Nreal) {
                    float* p0 = C + (size_t)m * ldC + n;
                    float* p1 = C + (size_t)(m + 8) * ldC + n;
                    p0[0] = acc[mf][nf][0]; p0[1] = acc[mf][nf][1];
                    p1[0] = acc[mf][nf][2]; p1[1] = acc[mf][nf][3];
                }
            } else if (mode == 1) {
                const int d = n % DQK_;
#pragma unroll
                for (int rr = 0; rr < 2; rr++) {
                    const int mr = m + rr * 8;
                    float x1 = acc[mf][nf][rr * 2 + 0] * qscale;
                    float x2 = acc[mf][nf][rr * 2 + 1] * qscale;
                    if (d >= DN_) {
                        const int j = (d - DN_) >> 1;
                        const float cc = g_cos[mr * 32 + j], ss = g_sin[mr * 32 + j];
                        const float o1 = x1 * cc - x2 * ss, o2 = x2 * cc + x1 * ss;
                        x1 = o1; x2 = o2;
                    }
                    __nv_bfloat16 h0, l0, h1, l1;
                    split2(x1, h0, l0); split2(x2, h1, l1);
                    const size_t off = (size_t)mr * ldC + n;
                    *(uint32_t*)(outH + off) = pack2(h0, h1);
                    *(uint32_t*)(outL + off) = pack2(l0, l1);
                }
            } else { // mode 2
                const int d = n & 255, hh = n >> 8;
#pragma unroll
                for (int rr = 0; rr < 2; rr++) {
                    const int mr = m + rr * 8;
                    const float x1 = acc[mf][nf][rr * 2 + 0];
                    const float x2 = acc[mf][nf][rr * 2 + 1];
                    if (d < DN_) {
                        const size_t off = ((size_t)mr * NH_ + hh) * DQK_ + d;
                        __nv_bfloat16 h0, l0, h1, l1;
                        split2(x1, h0, l0); split2(x2, h1, l1);
                        *(uint32_t*)(outH + off) = pack2(h0, h1);
                        *(uint32_t*)(outL + off) = pack2(l0, l1);
                    } else {
                        const size_t off = ((size_t)mr * NH_ + hh) * DV_ + (d - DN_);
                        *(float2*)(vout + off) = make_float2(x1, x2);
                    }
                }
            }
        }
    }
}

// ======================= rmsnorm (split bf16 output) =========================
__global__ void rmsnorm_split(const float* __restrict__ x, int srcStride, int srcOff, int W,
                              const float* __restrict__ w,
                              __nv_bfloat16* __restrict__ H, __nv_bfloat16* __restrict__ L) {
    const int row = blockIdx.x;
    const float* xr = x + (size_t)row * srcStride + srcOff;
    float ss = 0.f;
    for (int c = threadIdx.x; c < W; c += blockDim.x) {
        float v = xr[c];
        ss += v * v;
    }
    __shared__ float red[32];
#pragma unroll
    for (int o = 16; o; o >>= 1) ss += __shfl_xor_sync(0xffffffffu, ss, o);
    if ((threadIdx.x & 31) == 0) red[threadIdx.x >> 5] = ss;
    __syncthreads();
    if (threadIdx.x < 32) {
        float v = (threadIdx.x < (blockDim.x >> 5)) ? red[threadIdx.x] : 0.f;
#pragma unroll
        for (int o = 16; o; o >>= 1) v += __shfl_xor_sync(0xffffffffu, v, o);
        red[threadIdx.x] = v;
    }
    __syncthreads();
    const float rstd = rsqrtf(red[0] / (float)W + 1e-6f);
    for (int c = threadIdx.x; c < W; c += blockDim.x) {
        __nv_bfloat16 hh, ll;
        split2(xr[c] * rstd * w[c], hh, ll);
        H[(size_t)row * W + c] = hh;
        L[(size_t)row * W + c] = ll;
    }
}

// ======================= RoPE tables + k_pe broadcast ========================
__global__ void rope_tab_kernel(const int* __restrict__ pos) {
    const int t = blockIdx.x, i = threadIdx.x;
    double inv = pow(10000.0, -(double)i / 32.0);
    double f = (double)pos[t] * inv;
    double s, c;
    sincos(f, &s, &c);
    g_cos[t * 32 + i] = (float)c;
    g_sin[t * 32 + i] = (float)s;
}

// roped k_pe split + broadcast into g_kh/g_kl for all heads (d = 128..191)
__global__ void kpe_build_kernel() {
    const int t = blockIdx.x;
    const int i = threadIdx.x;   // pair 0..31
    const int hh = threadIdx.y;  // 0..7
    const float c = g_cos[t * 32 + i];
    const float s = g_sin[t * 32 + i];
    const float* src = g_qkv + (size_t)t * NQKV_ + (QLR_ + KVLR_) + 2 * i;
    const float x1 = src[0], x2 = src[1];
    const float o1 = x1 * c - x2 * s, o2 = x2 * c + x1 * s;
    __nv_bfloat16 h1, l1, h2, l2;
    split2(o1, h1, l1); split2(o2, h2, l2);
    const uint32_t hv = pack2(h1, h2), lv = pack2(l1, l2);
    for (int h = hh; h < NH_; h += 8) {
        const size_t off = ((size_t)t * NH_ + h) * DQK_ + DN_ + 2 * i;
        *(uint32_t*)(g_kh + off) = hv;
        *(uint32_t*)(g_kl + off) = lv;
    }
}

// v transpose + split: g_v [t][h][128] -> g_vth/g_vtl [h][d][t]
__global__ void vtrans_kernel() {
    __shared__ float tile[32][33];
    const int t0 = blockIdx.x * 32, d0 = blockIdx.y * 32, h = blockIdx.z;
    const int tx = threadIdx.x, ty = threadIdx.y; // 32 x 8
    for (int i = ty; i < 32; i += 8)
        tile[i][tx] = g_v[((size_t)(t0 + i) * NH_ + h) * DV_ + d0 + tx];
    __syncthreads();
    for (int i = ty; i < 32; i += 8) {
        __nv_bfloat16 hh, ll;
        split2(tile[tx][i], hh, ll);
        const size_t off = ((size_t)h * DV_ + d0 + i) * T_ + t0 + tx;
        g_vth[off] = hh; g_vtl[off] = ll;
    }
}

// ======================= HMMA flash attention (pipelined) ====================
#define QKP 200   // Q/K smem pitch (elems): 400B, conflict-free ldmatrix
#define PVP 72    // P/Vt pitch: 144B
#define SFP 68

struct ASmem {
    __nv_bfloat16 Qh[64 * QKP], Ql[64 * QKP];
    __nv_bfloat16 Kh[64 * QKP], Kl[64 * QKP];
    __nv_bfloat16 Vh[128 * PVP], Vl[128 * PVP];
    __nv_bfloat16 Ph[64 * PVP], Pl[64 * PVP];
    float Sf[64 * SFP];
    float rowM[64], rowL[64], rowScale[64];
};
#define ATTN_SMEM sizeof(ASmem)

__global__ void __launch_bounds__(256, 1)
attn_mma() {
    extern __shared__ char smem_raw[];
    ASmem& sm = *(ASmem*)smem_raw;
    const int h = blockIdx.x, qb = blockIdx.y;
    const int tid = threadIdx.x, wid = tid >> 5, lane = tid & 31;
    const int wm = wid & 3, wn = wid >> 2;
    const int t0 = qb * 64;
    const int lm = lane >> 2, ln = (lane & 3) * 2;

    const uint32_t sQh = smem_u32(sm.Qh), sQl = smem_u32(sm.Ql);
    const uint32_t sKh = smem_u32(sm.Kh), sKl = smem_u32(sm.Kl);
    const uint32_t sVh = smem_u32(sm.Vh), sVl = smem_u32(sm.Vl);
    const uint32_t sPh = smem_u32(sm.Ph), sPl = smem_u32(sm.Pl);

    auto loadK = [&](int kc) {
        const int tk0 = kc * 64;
        for (int idx = tid; idx < 64 * 24; idx += 256) {
            const int row = idx / 24, ch = idx % 24;
            const size_t go = ((size_t)(tk0 + row) * NH_ + h) * DQK_ + ch * 8;
            const uint32_t so = (row * QKP + ch * 8) * 2;
            CP_ASYNC16(sKh + so, g_kh + go);
            CP_ASYNC16(sKl + so, g_kl + go);
        }
    };
    auto loadV = [&](int kc) {
        const int tk0 = kc * 64;
        for (int idx = tid; idx < 128 * 8; idx += 256) {
            const int row = idx >> 3, ch = idx & 7;
            const size_t go = ((size_t)h * DV_ + row) * T_ + tk0 + ch * 8;
            const uint32_t so = (row * PVP + ch * 8) * 2;
            CP_ASYNC16(sVh + so, g_vth + go);
            CP_ASYNC16(sVl + so, g_vtl + go);
        }
    };

    // Q load (group 0), K0 (group 1), V0 (group 2)
    for (int idx = tid; idx < 64 * 24; idx += 256) {
        const int row = idx / 24, ch = idx % 24;
        const size_t go = ((size_t)(t0 + row) * NH_ + h) * DQK_ + ch * 8;
        const uint32_t so = (row * QKP + ch * 8) * 2;
        CP_ASYNC16(sQh + so, g_qh + go);
        CP_ASYNC16(sQl + so, g_ql + go);
    }
    CP_COMMIT();
    loadK(0); CP_COMMIT();
    loadV(0); CP_COMMIT();

    if (tid < 64) {
        sm.rowM[tid] = -1e30f;
        sm.rowL[tid] = 0.f;
    }

    const uint32_t aoffQ = ((wm * 16 + (lane & 15)) * QKP + ((lane >> 4) & 1) * 8) * 2;
    uint32_t boffK[4];
#pragma unroll
    for (int nf = 0; nf < 4; nf++)
        boffK[nf] = ((wn * 32 + nf * 8 + (lane & 7)) * QKP + ((lane >> 3) & 1) * 8) * 2;
    const uint32_t aoffP = ((wm * 16 + (lane & 15)) * PVP + ((lane >> 4) & 1) * 8) * 2;
    uint32_t boffV[8];
#pragma unroll
    for (int nf = 0; nf < 8; nf++)
        boffV[nf] = ((wn * 64 + nf * 8 + (lane & 7)) * PVP + ((lane >> 3) & 1) * 8) * 2;

    float accO[8][4];
#pragma unroll
    for (int i = 0; i < 8; i++)
#pragma unroll
        for (int q = 0; q < 4; q++) accO[i][q] = 0.f;

    for (int kc = 0; kc <= qb; kc++) {
        const int tk0 = kc * 64;
        // K(kc) ready (V(kc) may still be in flight)
        CP_WAIT1();
        __syncthreads();

        // ---- S = Q K^T ----
        float accS[4][4];
#pragma unroll
        for (int i = 0; i < 4; i++)
#pragma unroll
            for (int q = 0; q < 4; q++) accS[i][q] = 0.f;
#pragma unroll
        for (int ks = 0; ks < 12; ks++) {
            uint32_t ah[4], al[4];
            LDSM_X4(ah[0], ah[1], ah[2], ah[3], sQh + aoffQ + ks * 32);
            LDSM_X4(al[0], al[1], al[2], al[3], sQl + aoffQ + ks * 32);
#pragma unroll
            for (int nf = 0; nf < 4; nf++) {
                uint32_t bh[2], bl[2];
                LDSM_X2(bh[0], bh[1], sKh + boffK[nf] + ks * 32);
                LDSM_X2(bl[0], bl[1], sKl + boffK[nf] + ks * 32);
                MMA16816(accS[nf], ah, bh);
                MMA16816(accS[nf], ah, bl);
                MMA16816(accS[nf], al, bh);
            }
        }
        const bool diag = (kc == qb);
#pragma unroll
        for (int nf = 0; nf < 4; nf++) {
            const int r = wm * 16 + lm;
            const int c = wn * 32 + nf * 8 + ln;
            float v0 = accS[nf][0], v1 = accS[nf][1], v2 = accS[nf][2], v3 = accS[nf][3];
            if (diag) {
                const int rg0 = t0 + r, rg1 = rg0 + 8, cg = tk0 + c;
                if (cg > rg0) v0 = -1e30f;
                if (cg + 1 > rg0) v1 = -1e30f;
                if (cg > rg1) v2 = -1e30f;
                if (cg + 1 > rg1) v3 = -1e30f;
            }
            sm.Sf[r * SFP + c] = v0;
            sm.Sf[r * SFP + c + 1] = v1;
            sm.Sf[(r + 8) * SFP + c] = v2;
            sm.Sf[(r + 8) * SFP + c + 1] = v3;
        }
        __syncthreads();   // S written; K buffer free

        if (kc < qb) { loadK(kc + 1); CP_COMMIT(); }

        // ---- online softmax ----
        {
            const int row = tid >> 2, l4 = tid & 3;
            float mloc = -1e30f;
#pragma unroll
            for (int c = 0; c < 16; c++) mloc = fmaxf(mloc, sm.Sf[row * SFP + l4 * 16 + c]);
            mloc = fmaxf(mloc, __shfl_xor_sync(0xffffffffu, mloc, 1));
            mloc = fmaxf(mloc, __shfl_xor_sync(0xffffffffu, mloc, 2));
            const float mprev = sm.rowM[row];
            const float mnew = fmaxf(mprev, mloc);
            float lsum = 0.f;
#pragma unroll
            for (int c = 0; c < 16; c++) {
                const int col = l4 * 16 + c;
                const float p = __expf(sm.Sf[row * SFP + col] - mnew);
                lsum += p;
                __nv_bfloat16 hh, ll;
                split2(p, hh, ll);
                sm.Ph[row * PVP + col] = hh;
                sm.Pl[row * PVP + col] = ll;
            }
            lsum += __shfl_xor_sync(0xffffffffu, lsum, 1);
            lsum += __shfl_xor_sync(0xffffffffu, lsum, 2);
            if (l4 == 0) {
                const float sc = __expf(mprev - mnew);
                sm.rowScale[row] = sc;
                sm.rowM[row] = mnew;
                sm.rowL[row] = sm.rowL[row] * sc + lsum;
            }
        }

        // V(kc) ready (K(kc+1) may be in flight)
        if (kc < qb) { CP_WAIT1(); } else { CP_WAIT0(); }
        __syncthreads();

        // ---- rescale O, then O += P V ----
        const float s0 = sm.rowScale[wm * 16 + lm];
        const float s1 = sm.rowScale[wm * 16 + lm + 8];
#pragma unroll
        for (int nf = 0; nf < 8; nf++) {
            accO[nf][0] *= s0; accO[nf][1] *= s0;
            accO[nf][2] *= s1; accO[nf][3] *= s1;
        }
#pragma unroll
        for (int ks = 0; ks < 4; ks++) {
            uint32_t pah[4], pal[4];
            LDSM_X4(pah[0], pah[1], pah[2], pah[3], sPh + aoffP + ks * 32);
            LDSM_X4(pal[0], pal[1], pal[2], pal[3], sPl + aoffP + ks * 32);
#pragma unroll
            for (int nf = 0; nf < 8; nf++) {
                uint32_t vbh[2], vbl[2];
                LDSM_X2(vbh[0], vbh[1], sVh + boffV[nf] + ks * 32);
                LDSM_X2(vbl[0], vbl[1], sVl + boffV[nf] + ks * 32);
                MMA16816(accO[nf], pah, vbh);
                MMA16816(accO[nf], pah, vbl);
                MMA16816(accO[nf], pal, vbh);
            }
        }
        __syncthreads();   // V buffer free

        if (kc < qb) { loadV(kc + 1); CP_COMMIT(); }
    }

    // ---- finalize ----
    const float invL0 = 1.f / sm.rowL[wm * 16 + lm];
    const float invL1 = 1.f / sm.rowL[wm * 16 + lm + 8];
    const int r0g = t0 + wm * 16 + lm;
#pragma unroll
    for (int nf = 0; nf < 8; nf++) {
        const int col = h * DV_ + wn * 64 + nf * 8 + ln;
        __nv_bfloat16 h0, l0, h1, l1;
        split2(accO[nf][0] * invL0, h0, l0);
        split2(accO[nf][1] * invL0, h1, l1);
        *(uint32_t*)(g_ah + (size_t)r0g * (NH_ * DV_) + col) = pack2(h0, h1);
        *(uint32_t*)(g_al + (size_t)r0g * (NH_ * DV_) + col) = pack2(l0, l1);
        split2(accO[nf][2] * invL1, h0, l0);
        split2(accO[nf][3] * invL1, h1, l1);
        *(uint32_t*)(g_ah + (size_t)(r0g + 8) * (NH_ * DV_) + col) = pack2(h0, h1);
        *(uint32_t*)(g_al + (size_t)(r0g + 8) * (NH_ * DV_) + col) = pack2(l0, l1);
    }
}

// ======================= launch ==============================================
extern "C" void kernel_launch(void* const* d_in, const int* in_sizes, int n_in,
                              void* d_out, int out_size) {
    const int*   positions = (const int*)d_in[0];
    const float* hidden    = (const float*)d_in[1];
    const float* w_qkv_a   = (const float*)d_in[2];
    const float* q_a_ln_w  = (const float*)d_in[3];
    const float* w_q_b     = (const float*)d_in[4];
    const float* kv_a_ln_w = (const float*)d_in[5];
    const float* w_kv_b    = (const float*)d_in[6];
    const float* w_o       = (const float*)d_in[7];
    float* out = (float*)d_out;

    float *p_qkv, *p_v;
    cudaGetSymbolAddress((void**)&p_qkv, g_qkv);
    cudaGetSymbolAddress((void**)&p_v,   g_v);

    __nv_bfloat16 *w1h, *w1l, *w2h, *w2l, *w3h, *w3l, *w4h, *w4l, *ah, *al;
    __nv_bfloat16 *qanh, *qanl, *kvanh, *kvanl, *qh, *ql, *kh, *kl;
    cudaGetSymbolAddress((void**)&w1h, g_w1h); cudaGetSymbolAddress((void**)&w1l, g_w1l);
    cudaGetSymbolAddress((void**)&w2h, g_w2h); cudaGetSymbolAddress((void**)&w2l, g_w2l);
    cudaGetSymbolAddress((void**)&w3h, g_w3h); cudaGetSymbolAddress((void**)&w3l, g_w3l);
    cudaGetSymbolAddress((void**)&w4h, g_w4h); cudaGetSymbolAddress((void**)&w4l, g_w4l);
    cudaGetSymbolAddress((void**)&ah,  g_ah);  cudaGetSymbolAddress((void**)&al,  g_al);
    cudaGetSymbolAddress((void**)&qanh, g_qanh); cudaGetSymbolAddress((void**)&qanl, g_qanl);
    cudaGetSymbolAddress((void**)&kvanh, g_kvanh); cudaGetSymbolAddress((void**)&kvanl, g_kvanl);
    cudaGetSymbolAddress((void**)&qh, g_qh); cudaGetSymbolAddress((void**)&ql, g_ql);
    cudaGetSymbolAddress((void**)&kh, g_kh); cudaGetSymbolAddress((void**)&kl, g_kl);

    cudaFuncSetAttribute(gemm_hmma, cudaFuncAttributeMaxDynamicSharedMemorySize, GEMM_SMEM);
    cudaFuncSetAttribute(attn_mma, cudaFuncAttributeMaxDynamicSharedMemorySize, (int)ATTN_SMEM);

    // RoPE tables (only needs positions)
    rope_tab_kernel<<<T_, 32>>>(positions);

    // weight conversions (64x64 transpose + split)
    convBT_kernel<<<dim3(HID_ / 64, NQKV_PAD_ / 64), 256>>>(w_qkv_a, w1h, w1l, HID_, NQKV_);
    convBT_kernel<<<dim3(QLR_ / 64, (NH_ * DQK_) / 64), 256>>>(w_q_b, w2h, w2l, QLR_, NH_ * DQK_);
    convBT_kernel<<<dim3(KVLR_ / 64, (NH_ * DKV_) / 64), 256>>>(w_kv_b, w3h, w3l, KVLR_, NH_ * DKV_);
    convBT_kernel<<<dim3((NH_ * DV_) / 64, HID_ / 64), 256>>>(w_o, w4h, w4l, NH_ * DV_, HID_);

    // GEMM1: qkv = hidden @ w_qkv_a (fp32 out for rmsnorm + kpe)
    convA4_kernel<<<(T_ * HID_ / 4 + 255) / 256, 256>>>(hidden, ah, al, T_ * HID_ / 4);
    gemm_hmma<<<dim3(NQKV_PAD_ / 128, T_ / 128), 256, GEMM_SMEM>>>(
        ah, al, w1h, w1l, p_qkv, NQKV_, NQKV_, HID_, 0, nullptr, nullptr, nullptr);

    // rmsnorms -> split bf16
    rmsnorm_split<<<T_, 256>>>(p_qkv, NQKV_, 0,    QLR_,  q_a_ln_w,  qanh,  qanl);
    rmsnorm_split<<<T_, 256>>>(p_qkv, NQKV_, QLR_, KVLR_, kv_a_ln_w, kvanh, kvanl);

    // GEMM2 (fused RoPE+scale+split -> qh/ql) and GEMM3 (fused split k / fp32 v)
    gemm_hmma<<<dim3((NH_ * DQK_) / 128, T_ / 128), 256, GEMM_SMEM>>>(
        qanh, qanl, w2h, w2l, nullptr, NH_ * DQK_, NH_ * DQK_, QLR_, 1, qh, ql, nullptr);
    gemm_hmma<<<dim3((NH_ * DKV_) / 128, T_ / 128), 256, GEMM_SMEM>>>(
        kvanh, kvanl, w3h, w3l, nullptr, NH_ * DKV_, NH_ * DKV_, KVLR_, 2, kh, kl, p_v);

    // k_pe broadcast + V transpose
    kpe_build_kernel<<<T_, dim3(32, 8)>>>();
    vtrans_kernel<<<dim3(T_ / 32, DV_ / 32, NH_), dim3(32, 8)>>>();

    // attention -> g_ah/g_al (A operand of GEMM4)
    attn_mma<<<dim3(NH_, T_ / 64), 256, ATTN_SMEM>>>();

    // GEMM4: out = attn @ w_o
    gemm_hmma<<<dim3(HID_ / 128, T_ / 128), 256, GEMM_SMEM>>>(
        ah, al, w4h, w4l, out, HID_, HID_, NH_ * DV_, 0, nullptr, nullptr, nullptr);
}

// round 6
// speedup vs baseline: 3.6435x; 1.0138x over previous
#include <cuda_runtime.h>
#include <cuda_bf16.h>
#include <math.h>
#include <stdint.h>

#define T_   1024
#define HID_ 5120
#define NH_  128
#define DN_  128
#define DR_  64
#define DV_  128
#define QLR_ 1536
#define KVLR_ 512
#define DQK_ 192    // DN+DR
#define DKV_ 256    // DN+DV
#define NQKV_ 2112  // QLR+KVLR+DR
#define NQKV_PAD_ 2304

// ---------------- fp32 scratch ----------------------------------------------
__device__ float g_qkv [T_ * NQKV_];
__device__ float g_v   [T_ * NH_ * DV_];     // compact V from GEMM3 epilogue
__device__ float g_cos [T_ * 32];
__device__ float g_sin [T_ * 32];

// ---------------- bf16 split scratch ----------------------------------------
__device__ __nv_bfloat16 g_w1h[NQKV_PAD_ * HID_];
__device__ __nv_bfloat16 g_w1l[NQKV_PAD_ * HID_];
__device__ __nv_bfloat16 g_w2h[(NH_*DQK_) * QLR_];
__device__ __nv_bfloat16 g_w2l[(NH_*DQK_) * QLR_];
__device__ __nv_bfloat16 g_w3h[(NH_*DKV_) * KVLR_];
__device__ __nv_bfloat16 g_w3l[(NH_*DKV_) * KVLR_];
__device__ __nv_bfloat16 g_w4h[HID_ * (NH_*DV_)];
__device__ __nv_bfloat16 g_w4l[HID_ * (NH_*DV_)];
__device__ __nv_bfloat16 g_ah [T_ * (NH_*DV_)];      // A buf: hidden conv, then attn out
__device__ __nv_bfloat16 g_al [T_ * (NH_*DV_)];
__device__ __nv_bfloat16 g_qanh[T_ * QLR_], g_qanl[T_ * QLR_];
__device__ __nv_bfloat16 g_kvanh[T_ * KVLR_], g_kvanl[T_ * KVLR_];
__device__ __nv_bfloat16 g_qh[T_ * NH_ * DQK_], g_ql[T_ * NH_ * DQK_];
__device__ __nv_bfloat16 g_kh[T_ * NH_ * DQK_], g_kl[T_ * NH_ * DQK_];
__device__ __nv_bfloat16 g_vth[NH_ * DV_ * T_], g_vtl[NH_ * DV_ * T_];  // [h][d][t]

// ======================= PTX helpers =========================================
__device__ __forceinline__ uint32_t smem_u32(const void* p) {
    uint32_t a;
    asm("{ .reg .u64 t; cvta.to.shared.u64 t, %1; cvt.u32.u64 %0, t; }" : "=r"(a) : "l"(p));
    return a;
}

#define CP_ASYNC16(dst_u32, src_ptr) \
    asm volatile("cp.async.cg.shared.global [%0], [%1], 16;" :: "r"(dst_u32), "l"(src_ptr))
#define CP_COMMIT() asm volatile("cp.async.commit_group;" ::: "memory")
#define CP_WAIT1()  asm volatile("cp.async.wait_group 1;" ::: "memory")
#define CP_WAIT0()  asm volatile("cp.async.wait_group 0;" ::: "memory")

#define LDSM_X4(r0, r1, r2, r3, addr) \
    asm volatile("ldmatrix.sync.aligned.m8n8.x4.shared.b16 {%0,%1,%2,%3}, [%4];" \
        : "=r"(r0), "=r"(r1), "=r"(r2), "=r"(r3) : "r"(addr))
#define LDSM_X2(r0, r1, addr) \
    asm volatile("ldmatrix.sync.aligned.m8n8.x2.shared.b16 {%0,%1}, [%2];" \
        : "=r"(r0), "=r"(r1) : "r"(addr))

#define MMA16816(d, a, b) \
    asm volatile("mma.sync.aligned.m16n8k16.row.col.f32.bf16.bf16.f32 " \
        "{%0,%1,%2,%3},{%4,%5,%6,%7},{%8,%9},{%0,%1,%2,%3};" \
        : "+f"((d)[0]), "+f"((d)[1]), "+f"((d)[2]), "+f"((d)[3]) \
        : "r"((a)[0]), "r"((a)[1]), "r"((a)[2]), "r"((a)[3]), "r"((b)[0]), "r"((b)[1]))

// ======================= bf16 split conversion ===============================
__device__ __forceinline__ void split2(float v, __nv_bfloat16& h, __nv_bfloat16& l) {
    h = __float2bfloat16_rn(v);
    l = __float2bfloat16_rn(v - __bfloat162float(h));
}
__device__ __forceinline__ uint32_t pack2(__nv_bfloat16 a, __nv_bfloat16 b) {
    __nv_bfloat162 t(a, b);
    return *(uint32_t*)&t;
}

__global__ void convA4_kernel(const float* __restrict__ A,
                              __nv_bfloat16* __restrict__ H,
                              __nv_bfloat16* __restrict__ L, int n4) {
    int i = blockIdx.x * blockDim.x + threadIdx.x;
    if (i < n4) {
        float4 v = ((const float4*)A)[i];
        __nv_bfloat16 h0,l0,h1,l1,h2,l2,h3,l3;
        split2(v.x,h0,l0); split2(v.y,h1,l1); split2(v.z,h2,l2); split2(v.w,h3,l3);
        uint2 uh, ul;
        uh.x = pack2(h0,h1); uh.y = pack2(h2,h3);
        ul.x = pack2(l0,l1); ul.y = pack2(l2,l3);
        ((uint2*)H)[i] = uh; ((uint2*)L)[i] = ul;
    }
}

__global__ void convBT_kernel(const float* __restrict__ B,
                              __nv_bfloat16* __restrict__ TH,
                              __nv_bfloat16* __restrict__ TL,
                              int K, int N) {
    __shared__ float tile[64][65];
    const int k0 = blockIdx.x * 64, n0 = blockIdx.y * 64;
    const int tid = threadIdx.x; // 256
    for (int i = tid; i < 64 * 16; i += 256) {
        const int r = i >> 4, c4 = (i & 15) * 4;
        const int n = n0 + c4;
        float4 v = make_float4(0.f, 0.f, 0.f, 0.f);
        if (n < N) v = *(const float4*)(B + (size_t)(k0 + r) * N + n);
        tile[r][c4 + 0] = v.x; tile[r][c4 + 1] = v.y;
        tile[r][c4 + 2] = v.z; tile[r][c4 + 3] = v.w;
    }
    __syncthreads();
    for (int i = tid; i < 64 * 16; i += 256) {
        const int nr = i >> 4, kg = (i & 15) * 4;
        __nv_bfloat16 h0,l0,h1,l1,h2,l2,h3,l3;
        split2(tile[kg + 0][nr], h0, l0);
        split2(tile[kg + 1][nr], h1, l1);
        split2(tile[kg + 2][nr], h2, l2);
        split2(tile[kg + 3][nr], h3, l3);
        uint2 uh, ul;
        uh.x = pack2(h0,h1); uh.y = pack2(h2,h3);
        ul.x = pack2(l0,l1); ul.y = pack2(l2,l3);
        const size_t off = (size_t)(n0 + nr) * K + k0 + kg;
        *(uint2*)(TH + off) = uh;
        *(uint2*)(TL + off) = ul;
    }
}

// ======================= HMMA split GEMM with fused epilogues ================
// Inner loop register-caches fragments: per ks, Ah/Bh/Bl are LDSM'd once and
// reused across the 3 split terms (A regs reused for Al). 12KB smem reads per
// warp-chunk instead of 18KB.
#define GPITCH 80
#define GTILE  (128 * GPITCH)
#define GSTAGE (4 * GTILE)
#define GEMM_SMEM (2 * GSTAGE)

__global__ void __launch_bounds__(256, 2)
gemm_hmma(const __nv_bfloat16* __restrict__ Ah, const __nv_bfloat16* __restrict__ Al,
          const __nv_bfloat16* __restrict__ Bh, const __nv_bfloat16* __restrict__ Bl,
          float* __restrict__ C, int Nreal, int ldC, int K, int mode,
          __nv_bfloat16* __restrict__ outH, __nv_bfloat16* __restrict__ outL,
          float* __restrict__ vout) {
    extern __shared__ char smem[];
    const uint32_t sb = smem_u32(smem);
    const int tid  = threadIdx.x;
    const int wid  = tid >> 5;
    const int lane = tid & 31;
    const int wm   = wid & 1;
    const int wn   = wid >> 1;
    const int bm   = blockIdx.y * 128;
    const int bn   = blockIdx.x * 128;
    const int nchunks = K >> 5;

    const int r0c = tid >> 2, c40 = (tid & 3);

    auto issue = [&](int stage, int c) {
        const int k0 = c << 5;
        const uint32_t st = sb + stage * GSTAGE;
#pragma unroll
        for (int p = 0; p < 2; p++) {
            const int row = r0c + p * 64;
            const uint32_t doff = row * GPITCH + c40 * 16;
            const size_t goA = (size_t)(bm + row) * K + k0 + c40 * 8;
            const size_t goB = (size_t)(bn + row) * K + k0 + c40 * 8;
            CP_ASYNC16(st + 0 * GTILE + doff, Ah + goA);
            CP_ASYNC16(st + 1 * GTILE + doff, Al + goA);
            CP_ASYNC16(st + 2 * GTILE + doff, Bh + goB);
            CP_ASYNC16(st + 3 * GTILE + doff, Bl + goB);
        }
    };

    float acc[4][4][4];
#pragma unroll
    for (int i = 0; i < 4; i++)
#pragma unroll
        for (int j = 0; j < 4; j++)
#pragma unroll
            for (int q = 0; q < 4; q++) acc[i][j][q] = 0.f;

    uint32_t aoff[4], boff[4];
#pragma unroll
    for (int mf = 0; mf < 4; mf++) {
        const int row = wm * 64 + mf * 16 + (lane & 15);
        aoff[mf] = row * GPITCH + ((lane >> 4) & 1) * 16;
    }
#pragma unroll
    for (int nf = 0; nf < 4; nf++) {
        const int row = wn * 32 + nf * 8 + (lane & 7);
        boff[nf] = row * GPITCH + ((lane >> 3) & 1) * 16;
    }

    issue(0, 0);
    CP_COMMIT();
    if (nchunks > 1) issue(1, 1);
    CP_COMMIT();

    for (int c = 0; c < nchunks; c++) {
        CP_WAIT1();
        __syncthreads();
        const uint32_t st = sb + (c & 1) * GSTAGE;
#pragma unroll
        for (int ks = 0; ks < 2; ks++) {
            uint32_t a[4][4], bh[4][2], bl[4][2];
            // load Ah, Bh, Bl once
#pragma unroll
            for (int mf = 0; mf < 4; mf++)
                LDSM_X4(a[mf][0], a[mf][1], a[mf][2], a[mf][3],
                        st + 0 * GTILE + aoff[mf] + ks * 32);
#pragma unroll
            for (int nf = 0; nf < 4; nf++) {
                LDSM_X2(bh[nf][0], bh[nf][1], st + 2 * GTILE + boff[nf] + ks * 32);
                LDSM_X2(bl[nf][0], bl[nf][1], st + 3 * GTILE + boff[nf] + ks * 32);
            }
            // Ah*Bh + Ah*Bl
#pragma unroll
            for (int mf = 0; mf < 4; mf++)
#pragma unroll
                for (int nf = 0; nf < 4; nf++) {
                    MMA16816(acc[mf][nf], a[mf], bh[nf]);
                    MMA16816(acc[mf][nf], a[mf], bl[nf]);
                }
            // Al (reuse A registers) * Bh
#pragma unroll
            for (int mf = 0; mf < 4; mf++)
                LDSM_X4(a[mf][0], a[mf][1], a[mf][2], a[mf][3],
                        st + 1 * GTILE + aoff[mf] + ks * 32);
#pragma unroll
            for (int mf = 0; mf < 4; mf++)
#pragma unroll
                for (int nf = 0; nf < 4; nf++)
                    MMA16816(acc[mf][nf], a[mf], bh[nf]);
        }
        __syncthreads();
        if (c + 2 < nchunks) issue(c & 1, c + 2);
        CP_COMMIT();
    }

    const int lm = lane >> 2, ln = (lane & 3) * 2;
    const float qscale = 0.072168784f; // 1/sqrt(192)
#pragma unroll
    for (int mf = 0; mf < 4; mf++) {
#pragma unroll
        for (int nf = 0; nf < 4; nf++) {
            const int n = bn + wn * 32 + nf * 8 + ln;
            const int m = bm + wm * 64 + mf * 16 + lm;
            if (mode == 0) {
                if (n < Nreal) {
                    float* p0 = C + (size_t)m * ldC + n;
                    float* p1 = C + (size_t)(m + 8) * ldC + n;
                    p0[0] = acc[mf][nf][0]; p0[1] = acc[mf][nf][1];
                    p1[0] = acc[mf][nf][2]; p1[1] = acc[mf][nf][3];
                }
            } else if (mode == 1) {
                const int d = n % DQK_;
#pragma unroll
                for (int rr = 0; rr < 2; rr++) {
                    const int mr = m + rr * 8;
                    float x1 = acc[mf][nf][rr * 2 + 0] * qscale;
                    float x2 = acc[mf][nf][rr * 2 + 1] * qscale;
                    if (d >= DN_) {
                        const int j = (d - DN_) >> 1;
                        const float cc = g_cos[mr * 32 + j], ss = g_sin[mr * 32 + j];
                        const float o1 = x1 * cc - x2 * ss, o2 = x2 * cc + x1 * ss;
                        x1 = o1; x2 = o2;
                    }
                    __nv_bfloat16 h0, l0, h1, l1;
                    split2(x1, h0, l0); split2(x2, h1, l1);
                    const size_t off = (size_t)mr * ldC + n;
                    *(uint32_t*)(outH + off) = pack2(h0, h1);
                    *(uint32_t*)(outL + off) = pack2(l0, l1);
                }
            } else { // mode 2
                const int d = n & 255, hh = n >> 8;
#pragma unroll
                for (int rr = 0; rr < 2; rr++) {
                    const int mr = m + rr * 8;
                    const float x1 = acc[mf][nf][rr * 2 + 0];
                    const float x2 = acc[mf][nf][rr * 2 + 1];
                    if (d < DN_) {
                        const size_t off = ((size_t)mr * NH_ + hh) * DQK_ + d;
                        __nv_bfloat16 h0, l0, h1, l1;
                        split2(x1, h0, l0); split2(x2, h1, l1);
                        *(uint32_t*)(outH + off) = pack2(h0, h1);
                        *(uint32_t*)(outL + off) = pack2(l0, l1);
                    } else {
                        const size_t off = ((size_t)mr * NH_ + hh) * DV_ + (d - DN_);
                        *(float2*)(vout + off) = make_float2(x1, x2);
                    }
                }
            }
        }
    }
}

// ======================= rmsnorm (split bf16 output) =========================
__global__ void rmsnorm_split(const float* __restrict__ x, int srcStride, int srcOff, int W,
                              const float* __restrict__ w,
                              __nv_bfloat16* __restrict__ H, __nv_bfloat16* __restrict__ L) {
    const int row = blockIdx.x;
    const float* xr = x + (size_t)row * srcStride + srcOff;
    float ss = 0.f;
    for (int c = threadIdx.x; c < W; c += blockDim.x) {
        float v = xr[c];
        ss += v * v;
    }
    __shared__ float red[32];
#pragma unroll
    for (int o = 16; o; o >>= 1) ss += __shfl_xor_sync(0xffffffffu, ss, o);
    if ((threadIdx.x & 31) == 0) red[threadIdx.x >> 5] = ss;
    __syncthreads();
    if (threadIdx.x < 32) {
        float v = (threadIdx.x < (blockDim.x >> 5)) ? red[threadIdx.x] : 0.f;
#pragma unroll
        for (int o = 16; o; o >>= 1) v += __shfl_xor_sync(0xffffffffu, v, o);
        red[threadIdx.x] = v;
    }
    __syncthreads();
    const float rstd = rsqrtf(red[0] / (float)W + 1e-6f);
    for (int c = threadIdx.x; c < W; c += blockDim.x) {
        __nv_bfloat16 hh, ll;
        split2(xr[c] * rstd * w[c], hh, ll);
        H[(size_t)row * W + c] = hh;
        L[(size_t)row * W + c] = ll;
    }
}

// ======================= RoPE tables + k_pe broadcast ========================
__global__ void rope_tab_kernel(const int* __restrict__ pos) {
    const int t = blockIdx.x, i = threadIdx.x;
    double inv = pow(10000.0, -(double)i / 32.0);
    double f = (double)pos[t] * inv;
    double s, c;
    sincos(f, &s, &c);
    g_cos[t * 32 + i] = (float)c;
    g_sin[t * 32 + i] = (float)s;
}

__global__ void kpe_build_kernel() {
    const int t = blockIdx.x;
    const int i = threadIdx.x;   // pair 0..31
    const int hh = threadIdx.y;  // 0..7
    const float c = g_cos[t * 32 + i];
    const float s = g_sin[t * 32 + i];
    const float* src = g_qkv + (size_t)t * NQKV_ + (QLR_ + KVLR_) + 2 * i;
    const float x1 = src[0], x2 = src[1];
    const float o1 = x1 * c - x2 * s, o2 = x2 * c + x1 * s;
    __nv_bfloat16 h1, l1, h2, l2;
    split2(o1, h1, l1); split2(o2, h2, l2);
    const uint32_t hv = pack2(h1, h2), lv = pack2(l1, l2);
    for (int h = hh; h < NH_; h += 8) {
        const size_t off = ((size_t)t * NH_ + h) * DQK_ + DN_ + 2 * i;
        *(uint32_t*)(g_kh + off) = hv;
        *(uint32_t*)(g_kl + off) = lv;
    }
}

__global__ void vtrans_kernel() {
    __shared__ float tile[32][33];
    const int t0 = blockIdx.x * 32, d0 = blockIdx.y * 32, h = blockIdx.z;
    const int tx = threadIdx.x, ty = threadIdx.y; // 32 x 8
    for (int i = ty; i < 32; i += 8)
        tile[i][tx] = g_v[((size_t)(t0 + i) * NH_ + h) * DV_ + d0 + tx];
    __syncthreads();
    for (int i = ty; i < 32; i += 8) {
        __nv_bfloat16 hh, ll;
        split2(tile[tx][i], hh, ll);
        const size_t off = ((size_t)h * DV_ + d0 + i) * T_ + t0 + tx;
        g_vth[off] = hh; g_vtl[off] = ll;
    }
}

// ======================= HMMA flash attention (pipelined) ====================
#define QKP 200
#define PVP 72
#define SFP 68

struct ASmem {
    __nv_bfloat16 Qh[64 * QKP], Ql[64 * QKP];
    __nv_bfloat16 Kh[64 * QKP], Kl[64 * QKP];
    __nv_bfloat16 Vh[128 * PVP], Vl[128 * PVP];
    __nv_bfloat16 Ph[64 * PVP], Pl[64 * PVP];
    float Sf[64 * SFP];
    float rowM[64], rowL[64], rowScale[64];
};
#define ATTN_SMEM sizeof(ASmem)

__global__ void __launch_bounds__(256, 1)
attn_mma() {
    extern __shared__ char smem_raw[];
    ASmem& sm = *(ASmem*)smem_raw;
    const int h = blockIdx.x, qb = blockIdx.y;
    const int tid = threadIdx.x, wid = tid >> 5, lane = tid & 31;
    const int wm = wid & 3, wn = wid >> 2;
    const int t0 = qb * 64;
    const int lm = lane >> 2, ln = (lane & 3) * 2;

    const uint32_t sQh = smem_u32(sm.Qh), sQl = smem_u32(sm.Ql);
    const uint32_t sKh = smem_u32(sm.Kh), sKl = smem_u32(sm.Kl);
    const uint32_t sVh = smem_u32(sm.Vh), sVl = smem_u32(sm.Vl);
    const uint32_t sPh = smem_u32(sm.Ph), sPl = smem_u32(sm.Pl);

    auto loadK = [&](int kc) {
        const int tk0 = kc * 64;
        for (int idx = tid; idx < 64 * 24; idx += 256) {
            const int row = idx / 24, ch = idx % 24;
            const size_t go = ((size_t)(tk0 + row) * NH_ + h) * DQK_ + ch * 8;
            const uint32_t so = (row * QKP + ch * 8) * 2;
            CP_ASYNC16(sKh + so, g_kh + go);
            CP_ASYNC16(sKl + so, g_kl + go);
        }
    };
    auto loadV = [&](int kc) {
        const int tk0 = kc * 64;
        for (int idx = tid; idx < 128 * 8; idx += 256) {
            const int row = idx >> 3, ch = idx & 7;
            const size_t go = ((size_t)h * DV_ + row) * T_ + tk0 + ch * 8;
            const uint32_t so = (row * PVP + ch * 8) * 2;
            CP_ASYNC16(sVh + so, g_vth + go);
            CP_ASYNC16(sVl + so, g_vtl + go);
        }
    };

    for (int idx = tid; idx < 64 * 24; idx += 256) {
        const int row = idx / 24, ch = idx % 24;
        const size_t go = ((size_t)(t0 + row) * NH_ + h) * DQK_ + ch * 8;
        const uint32_t so = (row * QKP + ch * 8) * 2;
        CP_ASYNC16(sQh + so, g_qh + go);
        CP_ASYNC16(sQl + so, g_ql + go);
    }
    CP_COMMIT();
    loadK(0); CP_COMMIT();
    loadV(0); CP_COMMIT();

    if (tid < 64) {
        sm.rowM[tid] = -1e30f;
        sm.rowL[tid] = 0.f;
    }

    const uint32_t aoffQ = ((wm * 16 + (lane & 15)) * QKP + ((lane >> 4) & 1) * 8) * 2;
    uint32_t boffK[4];
#pragma unroll
    for (int nf = 0; nf < 4; nf++)
        boffK[nf] = ((wn * 32 + nf * 8 + (lane & 7)) * QKP + ((lane >> 3) & 1) * 8) * 2;
    const uint32_t aoffP = ((wm * 16 + (lane & 15)) * PVP + ((lane >> 4) & 1) * 8) * 2;
    uint32_t boffV[8];
#pragma unroll
    for (int nf = 0; nf < 8; nf++)
        boffV[nf] = ((wn * 64 + nf * 8 + (lane & 7)) * PVP + ((lane >> 3) & 1) * 8) * 2;

    float accO[8][4];
#pragma unroll
    for (int i = 0; i < 8; i++)
#pragma unroll
        for (int q = 0; q < 4; q++) accO[i][q] = 0.f;

    for (int kc = 0; kc <= qb; kc++) {
        const int tk0 = kc * 64;
        CP_WAIT1();
        __syncthreads();

        float accS[4][4];
#pragma unroll
        for (int i = 0; i < 4; i++)
#pragma unroll
            for (int q = 0; q < 4; q++) accS[i][q] = 0.f;
#pragma unroll
        for (int ks = 0; ks < 12; ks++) {
            uint32_t ah[4], al[4];
            LDSM_X4(ah[0], ah[1], ah[2], ah[3], sQh + aoffQ + ks * 32);
            LDSM_X4(al[0], al[1], al[2], al[3], sQl + aoffQ + ks * 32);
#pragma unroll
            for (int nf = 0; nf < 4; nf++) {
                uint32_t bh[2], bl[2];
                LDSM_X2(bh[0], bh[1], sKh + boffK[nf] + ks * 32);
                LDSM_X2(bl[0], bl[1], sKl + boffK[nf] + ks * 32);
                MMA16816(accS[nf], ah, bh);
                MMA16816(accS[nf], ah, bl);
                MMA16816(accS[nf], al, bh);
            }
        }
        const bool diag = (kc == qb);
#pragma unroll
        for (int nf = 0; nf < 4; nf++) {
            const int r = wm * 16 + lm;
            const int c = wn * 32 + nf * 8 + ln;
            float v0 = accS[nf][0], v1 = accS[nf][1], v2 = accS[nf][2], v3 = accS[nf][3];
            if (diag) {
                const int rg0 = t0 + r, rg1 = rg0 + 8, cg = tk0 + c;
                if (cg > rg0) v0 = -1e30f;
                if (cg + 1 > rg0) v1 = -1e30f;
                if (cg > rg1) v2 = -1e30f;
                if (cg + 1 > rg1) v3 = -1e30f;
            }
            sm.Sf[r * SFP + c] = v0;
            sm.Sf[r * SFP + c + 1] = v1;
            sm.Sf[(r + 8) * SFP + c] = v2;
            sm.Sf[(r + 8) * SFP + c + 1] = v3;
        }
        __syncthreads();

        if (kc < qb) { loadK(kc + 1); CP_COMMIT(); }

        {
            const int row = tid >> 2, l4 = tid & 3;
            float mloc = -1e30f;
#pragma unroll
            for (int c = 0; c < 16; c++) mloc = fmaxf(mloc, sm.Sf[row * SFP + l4 * 16 + c]);
            mloc = fmaxf(mloc, __shfl_xor_sync(0xffffffffu, mloc, 1));
            mloc = fmaxf(mloc, __shfl_xor_sync(0xffffffffu, mloc, 2));
            const float mprev = sm.rowM[row];
            const float mnew = fmaxf(mprev, mloc);
            float lsum = 0.f;
#pragma unroll
            for (int c = 0; c < 16; c++) {
                const int col = l4 * 16 + c;
                const float p = __expf(sm.Sf[row * SFP + col] - mnew);
                lsum += p;
                __nv_bfloat16 hh, ll;
                split2(p, hh, ll);
                sm.Ph[row * PVP + col] = hh;
                sm.Pl[row * PVP + col] = ll;
            }
            lsum += __shfl_xor_sync(0xffffffffu, lsum, 1);
            lsum += __shfl_xor_sync(0xffffffffu, lsum, 2);
            if (l4 == 0) {
                const float sc = __expf(mprev - mnew);
                sm.rowScale[row] = sc;
                sm.rowM[row] = mnew;
                sm.rowL[row] = sm.rowL[row] * sc + lsum;
            }
        }

        if (kc < qb) { CP_WAIT1(); } else { CP_WAIT0(); }
        __syncthreads();

        const float s0 = sm.rowScale[wm * 16 + lm];
        const float s1 = sm.rowScale[wm * 16 + lm + 8];
#pragma unroll
        for (int nf = 0; nf < 8; nf++) {
            accO[nf][0] *= s0; accO[nf][1] *= s0;
            accO[nf][2] *= s1; accO[nf][3] *= s1;
        }
#pragma unroll
        for (int ks = 0; ks < 4; ks++) {
            uint32_t pah[4], pal[4];
            LDSM_X4(pah[0], pah[1], pah[2], pah[3], sPh + aoffP + ks * 32);
            LDSM_X4(pal[0], pal[1], pal[2], pal[3], sPl + aoffP + ks * 32);
#pragma unroll
            for (int nf = 0; nf < 8; nf++) {
                uint32_t vbh[2], vbl[2];
                LDSM_X2(vbh[0], vbh[1], sVh + boffV[nf] + ks * 32);
                LDSM_X2(vbl[0], vbl[1], sVl + boffV[nf] + ks * 32);
                MMA16816(accO[nf], pah, vbh);
                MMA16816(accO[nf], pah, vbl);
                MMA16816(accO[nf], pal, vbh);
            }
        }
        __syncthreads();

        if (kc < qb) { loadV(kc + 1); CP_COMMIT(); }
    }

    const float invL0 = 1.f / sm.rowL[wm * 16 + lm];
    const float invL1 = 1.f / sm.rowL[wm * 16 + lm + 8];
    const int r0g = t0 + wm * 16 + lm;
#pragma unroll
    for (int nf = 0; nf < 8; nf++) {
        const int col = h * DV_ + wn * 64 + nf * 8 + ln;
        __nv_bfloat16 h0, l0, h1, l1;
        split2(accO[nf][0] * invL0, h0, l0);
        split2(accO[nf][1] * invL0, h1, l1);
        *(uint32_t*)(g_ah + (size_t)r0g * (NH_ * DV_) + col) = pack2(h0, h1);
        *(uint32_t*)(g_al + (size_t)r0g * (NH_ * DV_) + col) = pack2(l0, l1);
        split2(accO[nf][2] * invL1, h0, l0);
        split2(accO[nf][3] * invL1, h1, l1);
        *(uint32_t*)(g_ah + (size_t)(r0g + 8) * (NH_ * DV_) + col) = pack2(h0, h1);
        *(uint32_t*)(g_al + (size_t)(r0g + 8) * (NH_ * DV_) + col) = pack2(l0, l1);
    }
}

// ======================= launch ==============================================
extern "C" void kernel_launch(void* const* d_in, const int* in_sizes, int n_in,
                              void* d_out, int out_size) {
    const int*   positions = (const int*)d_in[0];
    const float* hidden    = (const float*)d_in[1];
    const float* w_qkv_a   = (const float*)d_in[2];
    const float* q_a_ln_w  = (const float*)d_in[3];
    const float* w_q_b     = (const float*)d_in[4];
    const float* kv_a_ln_w = (const float*)d_in[5];
    const float* w_kv_b    = (const float*)d_in[6];
    const float* w_o       = (const float*)d_in[7];
    float* out = (float*)d_out;

    float *p_qkv, *p_v;
    cudaGetSymbolAddress((void**)&p_qkv, g_qkv);
    cudaGetSymbolAddress((void**)&p_v,   g_v);

    __nv_bfloat16 *w1h, *w1l, *w2h, *w2l, *w3h, *w3l, *w4h, *w4l, *ah, *al;
    __nv_bfloat16 *qanh, *qanl, *kvanh, *kvanl, *qh, *ql, *kh, *kl;
    cudaGetSymbolAddress((void**)&w1h, g_w1h); cudaGetSymbolAddress((void**)&w1l, g_w1l);
    cudaGetSymbolAddress((void**)&w2h, g_w2h); cudaGetSymbolAddress((void**)&w2l, g_w2l);
    cudaGetSymbolAddress((void**)&w3h, g_w3h); cudaGetSymbolAddress((void**)&w3l, g_w3l);
    cudaGetSymbolAddress((void**)&w4h, g_w4h); cudaGetSymbolAddress((void**)&w4l, g_w4l);
    cudaGetSymbolAddress((void**)&ah,  g_ah);  cudaGetSymbolAddress((void**)&al,  g_al);
    cudaGetSymbolAddress((void**)&qanh, g_qanh); cudaGetSymbolAddress((void**)&qanl, g_qanl);
    cudaGetSymbolAddress((void**)&kvanh, g_kvanh); cudaGetSymbolAddress((void**)&kvanl, g_kvanl);
    cudaGetSymbolAddress((void**)&qh, g_qh); cudaGetSymbolAddress((void**)&ql, g_ql);
    cudaGetSymbolAddress((void**)&kh, g_kh); cudaGetSymbolAddress((void**)&kl, g_kl);

    cudaFuncSetAttribute(gemm_hmma, cudaFuncAttributeMaxDynamicSharedMemorySize, GEMM_SMEM);
    cudaFuncSetAttribute(attn_mma, cudaFuncAttributeMaxDynamicSharedMemorySize, (int)ATTN_SMEM);

    rope_tab_kernel<<<T_, 32>>>(positions);

    convBT_kernel<<<dim3(HID_ / 64, NQKV_PAD_ / 64), 256>>>(w_qkv_a, w1h, w1l, HID_, NQKV_);
    convBT_kernel<<<dim3(QLR_ / 64, (NH_ * DQK_) / 64), 256>>>(w_q_b, w2h, w2l, QLR_, NH_ * DQK_);
    convBT_kernel<<<dim3(KVLR_ / 64, (NH_ * DKV_) / 64), 256>>>(w_kv_b, w3h, w3l, KVLR_, NH_ * DKV_);
    convBT_kernel<<<dim3((NH_ * DV_) / 64, HID_ / 64), 256>>>(w_o, w4h, w4l, NH_ * DV_, HID_);

    convA4_kernel<<<(T_ * HID_ / 4 + 255) / 256, 256>>>(hidden, ah, al, T_ * HID_ / 4);
    gemm_hmma<<<dim3(NQKV_PAD_ / 128, T_ / 128), 256, GEMM_SMEM>>>(
        ah, al, w1h, w1l, p_qkv, NQKV_, NQKV_, HID_, 0, nullptr, nullptr, nullptr);

    rmsnorm_split<<<T_, 256>>>(p_qkv, NQKV_, 0,    QLR_,  q_a_ln_w,  qanh,  qanl);
    rmsnorm_split<<<T_, 256>>>(p_qkv, NQKV_, QLR_, KVLR_, kv_a_ln_w, kvanh, kvanl);

    gemm_hmma<<<dim3((NH_ * DQK_) / 128, T_ / 128), 256, GEMM_SMEM>>>(
        qanh, qanl, w2h, w2l, nullptr, NH_ * DQK_, NH_ * DQK_, QLR_, 1, qh, ql, nullptr);
    gemm_hmma<<<dim3((NH_ * DKV_) / 128, T_ / 128), 256, GEMM_SMEM>>>(
        kvanh, kvanl, w3h, w3l, nullptr, NH_ * DKV_, NH_ * DKV_, KVLR_, 2, kh, kl, p_v);

    kpe_build_kernel<<<T_, dim3(32, 8)>>>();
    vtrans_kernel<<<dim3(T_ / 32, DV_ / 32, NH_), dim3(32, 8)>>>();

    attn_mma<<<dim3(NH_, T_ / 64), 256, ATTN_SMEM>>>();

    gemm_hmma<<<dim3(HID_ / 128, T_ / 128), 256, GEMM_SMEM>>>(
        ah, al, w4h, w4l, out, HID_, HID_, NH_ * DV_, 0, nullptr, nullptr, nullptr);
}